// round 10
// baseline (speedup 1.0000x reference)
#include <cuda_runtime.h>
#include <cuda_fp16.h>
#include <math.h>
#include <stdint.h>

#define S_LEN  2048
#define B_SZ   2
#define H_DIM  4096
#define NHEADS 32
#define NGRP   2
#define HDIM   128
#define O_QKV  4608
#define M_ROWS 4096

// ---------------- scratch (__device__ globals; allocation-free rule) --------
__device__ __half g_mixed[M_ROWS * O_QKV];
__device__ __half g_ctx[M_ROWS * H_DIM];
__device__ __half g_hid[M_ROWS * H_DIM];
__device__ __half g_wq[O_QKV * H_DIM];
__device__ __half g_wd[H_DIM * H_DIM];

// ---------------- helpers ----------------------------------------------------
__device__ __forceinline__ uint32_t smem_u32(const void* p) {
    uint32_t a;
    asm("{ .reg .u64 t; cvta.to.shared.u64 t, %1; cvt.u32.u64 %0, t; }" : "=r"(a) : "l"(p));
    return a;
}
__device__ __forceinline__ void cp_async16(uint32_t dst, const void* src) {
    asm volatile("cp.async.cg.shared.global [%0], [%1], 16;" :: "r"(dst), "l"(src));
}
__device__ __forceinline__ void cp_commit() {
    asm volatile("cp.async.commit_group;" ::: "memory");
}
template<int N> __device__ __forceinline__ void cp_wait() {
    asm volatile("cp.async.wait_group %0;" :: "n"(N) : "memory");
}
// D += A*B, m16n8k16 fp16 in / fp32 acc
__device__ __forceinline__ void mma16(float* d, const uint32_t* a, uint32_t b0, uint32_t b1) {
    asm volatile("mma.sync.aligned.m16n8k16.row.col.f32.f16.f16.f32 "
        "{%0,%1,%2,%3}, {%4,%5,%6,%7}, {%8,%9}, {%0,%1,%2,%3};"
        : "+f"(d[0]), "+f"(d[1]), "+f"(d[2]), "+f"(d[3])
        : "r"(a[0]), "r"(a[1]), "r"(a[2]), "r"(a[3]), "r"(b0), "r"(b1));
}
#define LDSM4(r, addr) \
    asm volatile("ldmatrix.sync.aligned.m8n8.x4.shared.b16 {%0,%1,%2,%3}, [%4];" \
        : "=r"((r)[0]), "=r"((r)[1]), "=r"((r)[2]), "=r"((r)[3]) : "r"(addr))
#define LDSM4T(r, addr) \
    asm volatile("ldmatrix.sync.aligned.m8n8.x4.trans.shared.b16 {%0,%1,%2,%3}, [%4];" \
        : "=r"((r)[0]), "=r"((r)[1]), "=r"((r)[2]), "=r"((r)[3]) : "r"(addr))

__device__ __forceinline__ uint32_t h2u(__half2 h) { return *reinterpret_cast<uint32_t*>(&h); }
__device__ __forceinline__ uint32_t packh2(float lo, float hi) {
    __half2 h = __floats2half2_rn(lo, hi);        // low 16 bits = lo
    return *reinterpret_cast<uint32_t*>(&h);
}

// ---------------- f32 -> f16 rounding pass ----------------------------------
__global__ __launch_bounds__(256) void round_f16_kernel(
    const float4* __restrict__ in, __half2* __restrict__ out, int n4)
{
    int i = blockIdx.x * blockDim.x + threadIdx.x;
    if (i >= n4) return;
    float4 v = in[i];
    out[2 * i]     = __floats2half2_rn(v.x, v.y);
    out[2 * i + 1] = __floats2half2_rn(v.z, v.w);
}

// ---------------- fp16 mma GEMM: C[M,N] = A[M,K] @ W[N,K]^T (+bias) ---------
// 256 thr (8 warps, warp grid 2Mx4N, warp tile 64x64), CTA 128x256.
// K-chunk 64 halves, 3-stage cp.async, ldmatrix + register fragment
// double-buffering (kk+1 frags prefetched during kk's mma stream).
// smem rows padded to 72 halves (144 B).
#define A_STG_B (128 * 144)            // 18432
#define B_STG_B (256 * 144)            // 36864
#define STG_B   (A_STG_B + B_STG_B)    // 55296
#define GEMM_SMEM (3 * STG_B)          // 165888

__global__ __launch_bounds__(256, 1) void gemm_mma_kernel(
    const __half* __restrict__ A, const __half* __restrict__ W,
    const float* __restrict__ bias, void* __restrict__ Cv,
    int N, int K, int out_half)
{
    extern __shared__ char smc[];
    const uint32_t sb = smem_u32(smc);

    const int tid = threadIdx.x;
    const int wid = tid >> 5, lid = tid & 31;
    const int g = lid >> 2, c = lid & 3;
    const int m4 = lid >> 3, r8 = lid & 7;
    const int m0 = (wid & 1) * 64, n0 = (wid >> 1) * 64;
    const int row0 = blockIdx.y * 128;
    const int col0 = blockIdx.x * 256;

    // ldmatrix per-lane byte offsets
    const uint32_t laneA = ((m4 & 1) * 8 + r8) * 144 + (m4 >> 1) * 16;
    const uint32_t laneB = ((m4 >> 1) * 8 + r8) * 144 + (m4 & 1) * 16;

    float acc[4][8][4];
#pragma unroll
    for (int i = 0; i < 4; i++)
#pragma unroll
        for (int j = 0; j < 8; j++)
#pragma unroll
            for (int k = 0; k < 4; k++) acc[i][j][k] = 0.f;

    const int nchunk = K / 64;
    const int arow = tid >> 1;                 // 0..127 (2 thr/row, 4 segs each)
    const int aseg = (tid & 1) * 4;            // 0 or 4

#define LOADCH(ch, st) do {                                                    \
        const __half* _a = A + (size_t)(row0 + arow) * K + (ch) * 64;          \
        const __half* _b = W + (size_t)(col0 + tid) * K + (ch) * 64;           \
        uint32_t _da = sb + (st) * STG_B + arow * 144;                         \
        uint32_t _db = sb + (st) * STG_B + A_STG_B + tid * 144;                \
        cp_async16(_da + (aseg + 0) * 16, _a + (aseg + 0) * 8);                \
        cp_async16(_da + (aseg + 1) * 16, _a + (aseg + 1) * 8);                \
        cp_async16(_da + (aseg + 2) * 16, _a + (aseg + 2) * 8);                \
        cp_async16(_da + (aseg + 3) * 16, _a + (aseg + 3) * 8);                \
        cp_async16(_db,       _b);                                             \
        cp_async16(_db + 16,  _b + 8);                                         \
        cp_async16(_db + 32,  _b + 16);                                        \
        cp_async16(_db + 48,  _b + 24);                                        \
        cp_async16(_db + 64,  _b + 32);                                        \
        cp_async16(_db + 80,  _b + 40);                                        \
        cp_async16(_db + 96,  _b + 48);                                        \
        cp_async16(_db + 112, _b + 56);                                        \
        cp_commit();                                                           \
    } while (0)

    LOADCH(0, 0);
    LOADCH(1, 1);

    uint32_t af[2][4][4], bf[2][4][4];

    for (int i = 0; i < nchunk; i++) {
        if (i + 1 < nchunk) cp_wait<1>(); else cp_wait<0>();
        __syncthreads();
        if (i + 2 < nchunk) LOADCH(i + 2, (i + 2) % 3);

        const uint32_t stA = sb + (i % 3) * STG_B;
        const uint32_t stB = stA + A_STG_B;

        // preload kk=0 fragments
#pragma unroll
        for (int mt = 0; mt < 4; mt++)
            LDSM4(af[0][mt], stA + (m0 + mt * 16) * 144 + laneA);
#pragma unroll
        for (int nt = 0; nt < 4; nt++)
            LDSM4(bf[0][nt], stB + (n0 + nt * 16) * 144 + laneB);

#pragma unroll
        for (int kk = 0; kk < 4; kk++) {
            const int cur = kk & 1, nxt = cur ^ 1;
            if (kk < 3) {
                const int ko = (kk + 1) * 32;
#pragma unroll
                for (int mt = 0; mt < 4; mt++)
                    LDSM4(af[nxt][mt], stA + (m0 + mt * 16) * 144 + ko + laneA);
#pragma unroll
                for (int nt = 0; nt < 4; nt++)
                    LDSM4(bf[nxt][nt], stB + (n0 + nt * 16) * 144 + ko + laneB);
            }
#pragma unroll
            for (int mt = 0; mt < 4; mt++)
#pragma unroll
                for (int nt = 0; nt < 4; nt++) {
                    mma16(acc[mt][nt * 2],     af[cur][mt], bf[cur][nt][0], bf[cur][nt][1]);
                    mma16(acc[mt][nt * 2 + 1], af[cur][mt], bf[cur][nt][2], bf[cur][nt][3]);
                }
        }
    }
#undef LOADCH

    // epilogue
#pragma unroll
    for (int mt = 0; mt < 4; mt++) {
#pragma unroll
        for (int nt = 0; nt < 8; nt++) {
            const int rr = row0 + m0 + mt * 16 + g;
            const int cc = col0 + n0 + nt * 8 + 2 * c;
            float b0 = bias ? bias[cc] : 0.f;
            float b1 = bias ? bias[cc + 1] : 0.f;
            float v00 = acc[mt][nt][0] + b0, v01 = acc[mt][nt][1] + b1;
            float v10 = acc[mt][nt][2] + b0, v11 = acc[mt][nt][3] + b1;
            if (out_half) {
                __half* C = (__half*)Cv;
                *(__half2*)&C[(size_t)rr * N + cc]       = __floats2half2_rn(v00, v01);
                *(__half2*)&C[(size_t)(rr + 8) * N + cc] = __floats2half2_rn(v10, v11);
            } else {
                float* C = (float*)Cv;
                *(float2*)&C[(size_t)rr * N + cc]       = make_float2(v00, v01);
                *(float2*)&C[(size_t)(rr + 8) * N + cc] = make_float2(v10, v11);
            }
        }
    }
}

// ---------------- RoPE in place on g_mixed (half) ----------------------------
__global__ __launch_bounds__(256) void rope_kernel(const float* __restrict__ rope)
{
    int idx = blockIdx.x * blockDim.x + threadIdx.x;
    const int TOTAL = S_LEN * B_SZ * (NHEADS + NGRP) * 32;
    if (idx >= TOTAL) return;
    int i  = idx & 31;
    int t  = idx >> 5;
    int hh = t % (NHEADS + NGRP);
    int sb = t / (NHEADS + NGRP);
    int s  = sb >> 1;

    size_t row = (size_t)sb * O_QKV;
    int off = (hh < NHEADS) ? hh * HDIM : (NHEADS * HDIM + (hh - NHEADS) * HDIM);

    float cc = rope[s * 64 + 2 * i];
    float sn = rope[s * 64 + 2 * i + 1];
    __half2 xv = *(__half2*)&g_mixed[row + off + 2 * i];
    float x0 = __half2float(__low2half(xv));
    float x1 = __half2float(__high2half(xv));
    *(__half2*)&g_mixed[row + off + 2 * i] =
        __floats2half2_rn(x0 * cc - x1 * sn, x1 * cc + x0 * sn);
}

// ---------------- flash attention fp16, BQ=128, P-in-registers --------------
// 256 thr / 8 warps; warp w owns Q rows [w*16, w*16+16).
// K/V double-buffered via cp.async; V B-frags via ldmatrix.trans.
// smem: K0,K1,V0,V1 each 64 rows x 272 B (136-half stride) = 17408 B.
#define KB0 0
#define KB1 17408
#define VB0 34816
#define VB1 52224
#define FLASH_SMEM 69632

__global__ __launch_bounds__(256, 1) void flash_mma_kernel()
{
    extern __shared__ char smf[];
    const uint32_t sbase = smem_u32(smf);

    const int qb = blockIdx.x, h = blockIdx.y, b = blockIdx.z;
    const int grp = h >> 4;
    const int tid = threadIdx.x, wid = tid >> 5, lid = tid & 31;
    const int g = lid >> 2, c = lid & 3;
    const int m4 = lid >> 3, r8 = lid & 7;
    const int m0 = wid * 16;
    const float scale = 0.08838834764831843f;

    // ldmatrix.trans per-lane byte offset into a V buffer
    const uint32_t vlane = ((m4 & 1) * 8 + r8) * 272 + (m4 >> 1) * 16;

    // K/V tile loaders: 64 rows x 256 B = 1024 segs (4 per thread)
#define LOADK(kb, p) do {                                                       \
        _Pragma("unroll")                                                       \
        for (int _s = 0; _s < 4; _s++) {                                        \
            int _ln = tid + _s * 256;                                           \
            int _r = _ln >> 4, _c = _ln & 15;                                   \
            cp_async16(sbase + ((p) ? KB1 : KB0) + _r * 272 + _c * 16,          \
                &g_mixed[((size_t)(((kb) * 64 + _r) * 2 + b)) * O_QKV           \
                         + 4096 + grp * HDIM + _c * 8]);                        \
        } } while (0)
#define LOADV(kb, p) do {                                                       \
        _Pragma("unroll")                                                       \
        for (int _s = 0; _s < 4; _s++) {                                        \
            int _ln = tid + _s * 256;                                           \
            int _r = _ln >> 4, _c = _ln & 15;                                   \
            cp_async16(sbase + ((p) ? VB1 : VB0) + _r * 272 + _c * 16,          \
                &g_mixed[((size_t)(((kb) * 64 + _r) * 2 + b)) * O_QKV           \
                         + 4352 + grp * HDIM + _c * 8]);                        \
        } } while (0)

    // ---- stage Q (128 rows x 16 segs) through K0/V0, extract frags ----------
#pragma unroll
    for (int s = 0; s < 8; s++) {
        int ln = tid + s * 256;            // 0..2047
        int r = ln >> 4, cseg = ln & 15;
        uint32_t dst = (r < 64) ? (sbase + KB0 + r * 272 + cseg * 16)
                                : (sbase + VB0 + (r - 64) * 272 + cseg * 16);
        cp_async16(dst, &g_mixed[((size_t)((qb * 128 + r) * 2 + b)) * O_QKV
                                 + h * HDIM + cseg * 8]);
    }
    cp_commit();
    cp_wait<0>();
    __syncthreads();

    uint32_t qf[8][4];
    {
        const __half2* q2 = (const __half2*)(smf + ((wid < 4) ? KB0 : VB0));
        const int rl = (m0 & 63) + g;
#pragma unroll
        for (int kk = 0; kk < 8; kk++) {
            qf[kk][0] = h2u(q2[rl * 68 + kk * 8 + c]);
            qf[kk][1] = h2u(q2[(rl + 8) * 68 + kk * 8 + c]);
            qf[kk][2] = h2u(q2[rl * 68 + kk * 8 + c + 4]);
            qf[kk][3] = h2u(q2[(rl + 8) * 68 + kk * 8 + c + 4]);
        }
    }
    __syncthreads();   // all warps done reading before K0/V0 reload

    float o[16][4];
#pragma unroll
    for (int nt = 0; nt < 16; nt++)
#pragma unroll
        for (int j = 0; j < 4; j++) o[nt][j] = 0.f;
    float mst0 = -INFINITY, mst1 = -INFINITY, lst0 = 0.f, lst1 = 0.f;

    const int nkb = 2 * qb + 2;
    LOADK(0, 0); LOADV(0, 0); cp_commit();

    for (int kb = 0; kb < nkb; kb++) {
        const int p = kb & 1;
        cp_wait<0>();
        __syncthreads();
        if (kb + 1 < nkb) { LOADK(kb + 1, p ^ 1); LOADV(kb + 1, p ^ 1); cp_commit(); }

        const __half2* k2 = (const __half2*)(smf + (p ? KB1 : KB0));
        const uint32_t vbase = sbase + (p ? VB1 : VB0);

        // S = Q @ K^T  (16 rows x 64 cols per warp)
        float s[8][4];
#pragma unroll
        for (int nt = 0; nt < 8; nt++)
#pragma unroll
            for (int j = 0; j < 4; j++) s[nt][j] = 0.f;
#pragma unroll
        for (int kk = 0; kk < 8; kk++) {
#pragma unroll
            for (int nt = 0; nt < 8; nt++) {
                uint32_t b0 = h2u(k2[(nt * 8 + g) * 68 + kk * 8 + c]);
                uint32_t b1 = h2u(k2[(nt * 8 + g) * 68 + kk * 8 + c + 4]);
                mma16(s[nt], qf[kk], b0, b1);
            }
        }

        if (kb >= 2 * qb) {        // causal mask (diagonal region)
            const int r0 = qb * 128 + m0 + g, r1 = r0 + 8;
            const int cb = kb * 64;
#pragma unroll
            for (int nt = 0; nt < 8; nt++) {
                const int n = cb + nt * 8 + 2 * c;
                if (n > r0)     s[nt][0] = -1e30f;
                if (n + 1 > r0) s[nt][1] = -1e30f;
                if (n > r1)     s[nt][2] = -1e30f;
                if (n + 1 > r1) s[nt][3] = -1e30f;
            }
        }

        // online softmax, scale folded: p = exp((s - m) * scale)
        float rm0 = -INFINITY, rm1 = -INFINITY;
#pragma unroll
        for (int nt = 0; nt < 8; nt++) {
            rm0 = fmaxf(rm0, fmaxf(s[nt][0], s[nt][1]));
            rm1 = fmaxf(rm1, fmaxf(s[nt][2], s[nt][3]));
        }
        rm0 = fmaxf(rm0, __shfl_xor_sync(0xffffffffu, rm0, 1));
        rm0 = fmaxf(rm0, __shfl_xor_sync(0xffffffffu, rm0, 2));
        rm1 = fmaxf(rm1, __shfl_xor_sync(0xffffffffu, rm1, 1));
        rm1 = fmaxf(rm1, __shfl_xor_sync(0xffffffffu, rm1, 2));
        const float mn0 = fmaxf(mst0, rm0);
        const float mn1 = fmaxf(mst1, rm1);
        const float es0 = __expf((mst0 - mn0) * scale);
        const float es1 = __expf((mst1 - mn1) * scale);
        float rs0 = 0.f, rs1 = 0.f;
#pragma unroll
        for (int nt = 0; nt < 8; nt++) {
            s[nt][0] = __expf((s[nt][0] - mn0) * scale);
            s[nt][1] = __expf((s[nt][1] - mn0) * scale);
            s[nt][2] = __expf((s[nt][2] - mn1) * scale);
            s[nt][3] = __expf((s[nt][3] - mn1) * scale);
            rs0 += s[nt][0] + s[nt][1];
            rs1 += s[nt][2] + s[nt][3];
        }
        rs0 += __shfl_xor_sync(0xffffffffu, rs0, 1);
        rs0 += __shfl_xor_sync(0xffffffffu, rs0, 2);
        rs1 += __shfl_xor_sync(0xffffffffu, rs1, 1);
        rs1 += __shfl_xor_sync(0xffffffffu, rs1, 2);
        mst0 = mn0; mst1 = mn1;
        lst0 = lst0 * es0 + rs0;
        lst1 = lst1 * es1 + rs1;

        // O = O*escale + P @ V   (P built directly from s registers)
#pragma unroll
        for (int nt = 0; nt < 16; nt++) {
            o[nt][0] *= es0; o[nt][1] *= es0;
            o[nt][2] *= es1; o[nt][3] *= es1;
        }
#pragma unroll
        for (int kk = 0; kk < 4; kk++) {       // key-dim blocks of 16
            uint32_t a[4];
            a[0] = packh2(s[2 * kk][0],     s[2 * kk][1]);
            a[1] = packh2(s[2 * kk][2],     s[2 * kk][3]);
            a[2] = packh2(s[2 * kk + 1][0], s[2 * kk + 1][1]);
            a[3] = packh2(s[2 * kk + 1][2], s[2 * kk + 1][3]);
#pragma unroll
            for (int ntp = 0; ntp < 8; ntp++) {
                uint32_t vb[4];
                LDSM4T(vb, vbase + kk * 4352 + ntp * 32 + vlane);
                mma16(o[ntp * 2],     a, vb[0], vb[1]);
                mma16(o[ntp * 2 + 1], a, vb[2], vb[3]);
            }
        }
    }
#undef LOADK
#undef LOADV

    // normalize + write ctx (half, for the dense GEMM)
    const float inv0 = 1.f / lst0, inv1 = 1.f / lst1;
#pragma unroll
    for (int nt = 0; nt < 16; nt++) {
        const int ccol = h * HDIM + nt * 8 + 2 * c;
        size_t r0 = ((size_t)((qb * 128 + m0 + g) * 2 + b)) * H_DIM + ccol;
        size_t r1 = ((size_t)((qb * 128 + m0 + g + 8) * 2 + b)) * H_DIM + ccol;
        *(__half2*)&g_ctx[r0] = __floats2half2_rn(o[nt][0] * inv0, o[nt][1] * inv0);
        *(__half2*)&g_ctx[r1] = __floats2half2_rn(o[nt][2] * inv1, o[nt][3] * inv1);
    }
}

// ---------------------------------------------------------------------------
extern "C" void kernel_launch(void* const* d_in, const int* in_sizes, int n_in,
                              void* d_out, int out_size)
{
    const float* hidden = (const float*)d_in[0];
    const float* rope   = (const float*)d_in[2];
    const float* Wqkv   = (const float*)d_in[3];
    const float* bqkv   = (const float*)d_in[4];
    const float* Wd     = (const float*)d_in[5];
    float* out = (float*)d_out;

    __half *mixed, *ctx, *hid, *wq, *wd;
    cudaGetSymbolAddress((void**)&mixed, g_mixed);
    cudaGetSymbolAddress((void**)&ctx,   g_ctx);
    cudaGetSymbolAddress((void**)&hid,   g_hid);
    cudaGetSymbolAddress((void**)&wq,    g_wq);
    cudaGetSymbolAddress((void**)&wd,    g_wd);

    cudaFuncSetAttribute(gemm_mma_kernel,
                         cudaFuncAttributeMaxDynamicSharedMemorySize, GEMM_SMEM);
    cudaFuncSetAttribute(flash_mma_kernel,
                         cudaFuncAttributeMaxDynamicSharedMemorySize, FLASH_SMEM);

    // fp16 pre-rounding (RNE) of GEMM inputs
    {
        int n4 = M_ROWS * H_DIM / 4;
        round_f16_kernel<<<n4 / 256, 256>>>((const float4*)hidden, (__half2*)hid, n4);
    }
    {
        int n4 = O_QKV * H_DIM / 4;
        round_f16_kernel<<<n4 / 256, 256>>>((const float4*)Wqkv, (__half2*)wq, n4);
    }
    {
        int n4 = H_DIM * H_DIM / 4;
        round_f16_kernel<<<n4 / 256, 256>>>((const float4*)Wd, (__half2*)wd, n4);
    }

    // 1) QKV projection + bias (half output -> flash consumes directly)
    gemm_mma_kernel<<<dim3(O_QKV / 256, M_ROWS / 128), 256, GEMM_SMEM>>>(
        hid, wq, bqkv, mixed, O_QKV, H_DIM, 1);

    // 2) RoPE (half in/out)
    const int total = S_LEN * B_SZ * (NHEADS + NGRP) * 32;
    rope_kernel<<<(total + 255) / 256, 256>>>(rope);

    // 3) flash attention (fp16, P in registers)
    flash_mma_kernel<<<dim3(S_LEN / 128, NHEADS, B_SZ), 256, FLASH_SMEM>>>();

    // 4) dense projection (fp32 output)
    gemm_mma_kernel<<<dim3(H_DIM / 256, M_ROWS / 128), 256, GEMM_SMEM>>>(
        ctx, wd, nullptr, out, H_DIM, H_DIM, 0);
}

// round 11
// speedup vs baseline: 1.1393x; 1.1393x over previous
#include <cuda_runtime.h>
#include <cuda_fp16.h>
#include <math.h>
#include <stdint.h>

#define S_LEN  2048
#define B_SZ   2
#define H_DIM  4096
#define NHEADS 32
#define NGRP   2
#define HDIM   128
#define O_QKV  4608
#define M_ROWS 4096

// ---------------- scratch (__device__ globals; allocation-free rule) --------
__device__ __half g_mixed[M_ROWS * O_QKV];
__device__ __half g_ctx[M_ROWS * H_DIM];
__device__ __half g_hid[M_ROWS * H_DIM];
__device__ __half g_wq[O_QKV * H_DIM];
__device__ __half g_wd[H_DIM * H_DIM];

// ---------------- helpers ----------------------------------------------------
__device__ __forceinline__ uint32_t smem_u32(const void* p) {
    uint32_t a;
    asm("{ .reg .u64 t; cvta.to.shared.u64 t, %1; cvt.u32.u64 %0, t; }" : "=r"(a) : "l"(p));
    return a;
}
__device__ __forceinline__ void cp_async16(uint32_t dst, const void* src) {
    asm volatile("cp.async.cg.shared.global [%0], [%1], 16;" :: "r"(dst), "l"(src));
}
__device__ __forceinline__ void cp_commit() {
    asm volatile("cp.async.commit_group;" ::: "memory");
}
template<int N> __device__ __forceinline__ void cp_wait() {
    asm volatile("cp.async.wait_group %0;" :: "n"(N) : "memory");
}
// D += A*B, m16n8k16 fp16 in / fp32 acc
__device__ __forceinline__ void mma16(float* d, const uint32_t* a, uint32_t b0, uint32_t b1) {
    asm volatile("mma.sync.aligned.m16n8k16.row.col.f32.f16.f16.f32 "
        "{%0,%1,%2,%3}, {%4,%5,%6,%7}, {%8,%9}, {%0,%1,%2,%3};"
        : "+f"(d[0]), "+f"(d[1]), "+f"(d[2]), "+f"(d[3])
        : "r"(a[0]), "r"(a[1]), "r"(a[2]), "r"(a[3]), "r"(b0), "r"(b1));
}
#define LDSM4(r, addr) \
    asm volatile("ldmatrix.sync.aligned.m8n8.x4.shared.b16 {%0,%1,%2,%3}, [%4];" \
        : "=r"((r)[0]), "=r"((r)[1]), "=r"((r)[2]), "=r"((r)[3]) : "r"(addr))
#define LDSM4T(r, addr) \
    asm volatile("ldmatrix.sync.aligned.m8n8.x4.trans.shared.b16 {%0,%1,%2,%3}, [%4];" \
        : "=r"((r)[0]), "=r"((r)[1]), "=r"((r)[2]), "=r"((r)[3]) : "r"(addr))

__device__ __forceinline__ uint32_t h2u(__half2 h) { return *reinterpret_cast<uint32_t*>(&h); }
__device__ __forceinline__ uint32_t packh2(float lo, float hi) {
    __half2 h = __floats2half2_rn(lo, hi);        // low 16 bits = lo
    return *reinterpret_cast<uint32_t*>(&h);
}

// ---------------- f32 -> f16 rounding pass ----------------------------------
__global__ __launch_bounds__(256) void round_f16_kernel(
    const float4* __restrict__ in, __half2* __restrict__ out, int n4)
{
    int i = blockIdx.x * blockDim.x + threadIdx.x;
    if (i >= n4) return;
    float4 v = in[i];
    out[2 * i]     = __floats2half2_rn(v.x, v.y);
    out[2 * i + 1] = __floats2half2_rn(v.z, v.w);
}

// ---------------- fp16 mma GEMM: C[M,N] = A[M,K] @ W[N,K]^T (+bias) ---------
// CTA 128x128, 256 thr (8 warps, warp grid 2Mx4N, warp tile 64x32),
// K-chunk 64 halves, 3-stage cp.async, 2 CTAs/SM (stall interleaving).
// smem rows padded to 72 halves (144 B).
#define A_STG_B (128 * 144)            // 18432
#define B_STG_B (128 * 144)            // 18432
#define STG_B   (A_STG_B + B_STG_B)    // 36864
#define GEMM_SMEM (3 * STG_B)          // 110592

__global__ __launch_bounds__(256, 2) void gemm_mma_kernel(
    const __half* __restrict__ A, const __half* __restrict__ W,
    const float* __restrict__ bias, void* __restrict__ Cv,
    int N, int K, int out_half)
{
    extern __shared__ char smc[];
    const uint32_t sb = smem_u32(smc);

    const int tid = threadIdx.x;
    const int wid = tid >> 5, lid = tid & 31;
    const int g = lid >> 2, c = lid & 3;
    const int m4 = lid >> 3, r8 = lid & 7;
    const int m0 = (wid & 1) * 64, n0 = (wid >> 1) * 32;
    const int row0 = blockIdx.y * 128;
    const int col0 = blockIdx.x * 128;

    // ldmatrix per-lane byte offsets
    const uint32_t laneA = ((m4 & 1) * 8 + r8) * 144 + (m4 >> 1) * 16;
    const uint32_t laneB = ((m4 >> 1) * 8 + r8) * 144 + (m4 & 1) * 16;

    float acc[4][4][4];
#pragma unroll
    for (int i = 0; i < 4; i++)
#pragma unroll
        for (int j = 0; j < 4; j++)
#pragma unroll
            for (int k = 0; k < 4; k++) acc[i][j][k] = 0.f;

    const int nchunk = K / 64;
    const int arow = tid >> 1;                 // 0..127 (2 thr/row, 4 segs each)
    const int aseg = (tid & 1) * 4;            // 0 or 4

#define LOADCH(ch, st) do {                                                    \
        const __half* _a = A + (size_t)(row0 + arow) * K + (ch) * 64;          \
        const __half* _b = W + (size_t)(col0 + arow) * K + (ch) * 64;          \
        uint32_t _da = sb + (st) * STG_B + arow * 144;                         \
        uint32_t _db = sb + (st) * STG_B + A_STG_B + arow * 144;               \
        cp_async16(_da + (aseg + 0) * 16, _a + (aseg + 0) * 8);                \
        cp_async16(_da + (aseg + 1) * 16, _a + (aseg + 1) * 8);                \
        cp_async16(_da + (aseg + 2) * 16, _a + (aseg + 2) * 8);                \
        cp_async16(_da + (aseg + 3) * 16, _a + (aseg + 3) * 8);                \
        cp_async16(_db + (aseg + 0) * 16, _b + (aseg + 0) * 8);                \
        cp_async16(_db + (aseg + 1) * 16, _b + (aseg + 1) * 8);                \
        cp_async16(_db + (aseg + 2) * 16, _b + (aseg + 2) * 8);                \
        cp_async16(_db + (aseg + 3) * 16, _b + (aseg + 3) * 8);                \
        cp_commit();                                                           \
    } while (0)

    LOADCH(0, 0);
    LOADCH(1, 1);

    for (int i = 0; i < nchunk; i++) {
        if (i + 1 < nchunk) cp_wait<1>(); else cp_wait<0>();
        __syncthreads();
        if (i + 2 < nchunk) LOADCH(i + 2, (i + 2) % 3);

        const uint32_t stA = sb + (i % 3) * STG_B;
        const uint32_t stB = stA + A_STG_B;
#pragma unroll
        for (int kk = 0; kk < 4; kk++) {
            uint32_t af[4][4], bf[2][4];
#pragma unroll
            for (int mt = 0; mt < 4; mt++)
                LDSM4(af[mt], stA + (m0 + mt * 16) * 144 + kk * 32 + laneA);
#pragma unroll
            for (int np = 0; np < 2; np++)
                LDSM4(bf[np], stB + (n0 + np * 16) * 144 + kk * 32 + laneB);
#pragma unroll
            for (int mt = 0; mt < 4; mt++)
#pragma unroll
                for (int np = 0; np < 2; np++) {
                    mma16(acc[mt][np * 2],     af[mt], bf[np][0], bf[np][1]);
                    mma16(acc[mt][np * 2 + 1], af[mt], bf[np][2], bf[np][3]);
                }
        }
    }
#undef LOADCH

    // epilogue
#pragma unroll
    for (int mt = 0; mt < 4; mt++) {
#pragma unroll
        for (int nt = 0; nt < 4; nt++) {
            const int rr = row0 + m0 + mt * 16 + g;
            const int cc = col0 + n0 + nt * 8 + 2 * c;
            float b0 = bias ? bias[cc] : 0.f;
            float b1 = bias ? bias[cc + 1] : 0.f;
            float v00 = acc[mt][nt][0] + b0, v01 = acc[mt][nt][1] + b1;
            float v10 = acc[mt][nt][2] + b0, v11 = acc[mt][nt][3] + b1;
            if (out_half) {
                __half* C = (__half*)Cv;
                *(__half2*)&C[(size_t)rr * N + cc]       = __floats2half2_rn(v00, v01);
                *(__half2*)&C[(size_t)(rr + 8) * N + cc] = __floats2half2_rn(v10, v11);
            } else {
                float* C = (float*)Cv;
                *(float2*)&C[(size_t)rr * N + cc]       = make_float2(v00, v01);
                *(float2*)&C[(size_t)(rr + 8) * N + cc] = make_float2(v10, v11);
            }
        }
    }
}

// ---------------- RoPE in place on g_mixed (half) ----------------------------
__global__ __launch_bounds__(256) void rope_kernel(const float* __restrict__ rope)
{
    int idx = blockIdx.x * blockDim.x + threadIdx.x;
    const int TOTAL = S_LEN * B_SZ * (NHEADS + NGRP) * 32;
    if (idx >= TOTAL) return;
    int i  = idx & 31;
    int t  = idx >> 5;
    int hh = t % (NHEADS + NGRP);
    int sb = t / (NHEADS + NGRP);
    int s  = sb >> 1;

    size_t row = (size_t)sb * O_QKV;
    int off = (hh < NHEADS) ? hh * HDIM : (NHEADS * HDIM + (hh - NHEADS) * HDIM);

    float cc = rope[s * 64 + 2 * i];
    float sn = rope[s * 64 + 2 * i + 1];
    __half2 xv = *(__half2*)&g_mixed[row + off + 2 * i];
    float x0 = __half2float(__low2half(xv));
    float x1 = __half2float(__high2half(xv));
    *(__half2*)&g_mixed[row + off + 2 * i] =
        __floats2half2_rn(x0 * cc - x1 * sn, x1 * cc + x0 * sn);
}

// ---------------- flash attention fp16, BQ=128, P-in-registers --------------
// 256 thr / 8 warps; warp w owns Q rows [w*16, w*16+16).
// K/V double-buffered via cp.async; V B-frags via ldmatrix.trans.
// smem: K0,K1,V0,V1 each 64 rows x 272 B (136-half stride) = 17408 B.
#define KB0 0
#define KB1 17408
#define VB0 34816
#define VB1 52224
#define FLASH_SMEM 69632

__global__ __launch_bounds__(256, 1) void flash_mma_kernel()
{
    extern __shared__ char smf[];
    const uint32_t sbase = smem_u32(smf);

    const int qb = blockIdx.x, h = blockIdx.y, b = blockIdx.z;
    const int grp = h >> 4;
    const int tid = threadIdx.x, wid = tid >> 5, lid = tid & 31;
    const int g = lid >> 2, c = lid & 3;
    const int m4 = lid >> 3, r8 = lid & 7;
    const int m0 = wid * 16;
    const float scale = 0.08838834764831843f;

    // ldmatrix.trans per-lane byte offset into a V buffer
    const uint32_t vlane = ((m4 & 1) * 8 + r8) * 272 + (m4 >> 1) * 16;

    // K/V tile loaders: 64 rows x 256 B = 1024 segs (4 per thread)
#define LOADK(kb, p) do {                                                       \
        _Pragma("unroll")                                                       \
        for (int _s = 0; _s < 4; _s++) {                                        \
            int _ln = tid + _s * 256;                                           \
            int _r = _ln >> 4, _c = _ln & 15;                                   \
            cp_async16(sbase + ((p) ? KB1 : KB0) + _r * 272 + _c * 16,          \
                &g_mixed[((size_t)(((kb) * 64 + _r) * 2 + b)) * O_QKV           \
                         + 4096 + grp * HDIM + _c * 8]);                        \
        } } while (0)
#define LOADV(kb, p) do {                                                       \
        _Pragma("unroll")                                                       \
        for (int _s = 0; _s < 4; _s++) {                                        \
            int _ln = tid + _s * 256;                                           \
            int _r = _ln >> 4, _c = _ln & 15;                                   \
            cp_async16(sbase + ((p) ? VB1 : VB0) + _r * 272 + _c * 16,          \
                &g_mixed[((size_t)(((kb) * 64 + _r) * 2 + b)) * O_QKV           \
                         + 4352 + grp * HDIM + _c * 8]);                        \
        } } while (0)

    // ---- stage Q (128 rows x 16 segs) through K0/V0, extract frags ----------
#pragma unroll
    for (int s = 0; s < 8; s++) {
        int ln = tid + s * 256;            // 0..2047
        int r = ln >> 4, cseg = ln & 15;
        uint32_t dst = (r < 64) ? (sbase + KB0 + r * 272 + cseg * 16)
                                : (sbase + VB0 + (r - 64) * 272 + cseg * 16);
        cp_async16(dst, &g_mixed[((size_t)((qb * 128 + r) * 2 + b)) * O_QKV
                                 + h * HDIM + cseg * 8]);
    }
    cp_commit();
    cp_wait<0>();
    __syncthreads();

    uint32_t qf[8][4];
    {
        const __half2* q2 = (const __half2*)(smf + ((wid < 4) ? KB0 : VB0));
        const int rl = (m0 & 63) + g;
#pragma unroll
        for (int kk = 0; kk < 8; kk++) {
            qf[kk][0] = h2u(q2[rl * 68 + kk * 8 + c]);
            qf[kk][1] = h2u(q2[(rl + 8) * 68 + kk * 8 + c]);
            qf[kk][2] = h2u(q2[rl * 68 + kk * 8 + c + 4]);
            qf[kk][3] = h2u(q2[(rl + 8) * 68 + kk * 8 + c + 4]);
        }
    }
    __syncthreads();   // all warps done reading before K0/V0 reload

    float o[16][4];
#pragma unroll
    for (int nt = 0; nt < 16; nt++)
#pragma unroll
        for (int j = 0; j < 4; j++) o[nt][j] = 0.f;
    float mst0 = -INFINITY, mst1 = -INFINITY, lst0 = 0.f, lst1 = 0.f;

    const int nkb = 2 * qb + 2;
    LOADK(0, 0); LOADV(0, 0); cp_commit();

    for (int kb = 0; kb < nkb; kb++) {
        const int p = kb & 1;
        cp_wait<0>();
        __syncthreads();
        if (kb + 1 < nkb) { LOADK(kb + 1, p ^ 1); LOADV(kb + 1, p ^ 1); cp_commit(); }

        const __half2* k2 = (const __half2*)(smf + (p ? KB1 : KB0));
        const uint32_t vbase = sbase + (p ? VB1 : VB0);

        // S = Q @ K^T  (16 rows x 64 cols per warp)
        float s[8][4];
#pragma unroll
        for (int nt = 0; nt < 8; nt++)
#pragma unroll
            for (int j = 0; j < 4; j++) s[nt][j] = 0.f;
#pragma unroll
        for (int kk = 0; kk < 8; kk++) {
#pragma unroll
            for (int nt = 0; nt < 8; nt++) {
                uint32_t b0 = h2u(k2[(nt * 8 + g) * 68 + kk * 8 + c]);
                uint32_t b1 = h2u(k2[(nt * 8 + g) * 68 + kk * 8 + c + 4]);
                mma16(s[nt], qf[kk], b0, b1);
            }
        }

        if (kb >= 2 * qb) {        // causal mask (diagonal region)
            const int r0 = qb * 128 + m0 + g, r1 = r0 + 8;
            const int cb = kb * 64;
#pragma unroll
            for (int nt = 0; nt < 8; nt++) {
                const int n = cb + nt * 8 + 2 * c;
                if (n > r0)     s[nt][0] = -1e30f;
                if (n + 1 > r0) s[nt][1] = -1e30f;
                if (n > r1)     s[nt][2] = -1e30f;
                if (n + 1 > r1) s[nt][3] = -1e30f;
            }
        }

        // online softmax, scale folded: p = exp((s - m) * scale)
        float rm0 = -INFINITY, rm1 = -INFINITY;
#pragma unroll
        for (int nt = 0; nt < 8; nt++) {
            rm0 = fmaxf(rm0, fmaxf(s[nt][0], s[nt][1]));
            rm1 = fmaxf(rm1, fmaxf(s[nt][2], s[nt][3]));
        }
        rm0 = fmaxf(rm0, __shfl_xor_sync(0xffffffffu, rm0, 1));
        rm0 = fmaxf(rm0, __shfl_xor_sync(0xffffffffu, rm0, 2));
        rm1 = fmaxf(rm1, __shfl_xor_sync(0xffffffffu, rm1, 1));
        rm1 = fmaxf(rm1, __shfl_xor_sync(0xffffffffu, rm1, 2));
        const float mn0 = fmaxf(mst0, rm0);
        const float mn1 = fmaxf(mst1, rm1);
        const float es0 = __expf((mst0 - mn0) * scale);
        const float es1 = __expf((mst1 - mn1) * scale);
        float rs0 = 0.f, rs1 = 0.f;
#pragma unroll
        for (int nt = 0; nt < 8; nt++) {
            s[nt][0] = __expf((s[nt][0] - mn0) * scale);
            s[nt][1] = __expf((s[nt][1] - mn0) * scale);
            s[nt][2] = __expf((s[nt][2] - mn1) * scale);
            s[nt][3] = __expf((s[nt][3] - mn1) * scale);
            rs0 += s[nt][0] + s[nt][1];
            rs1 += s[nt][2] + s[nt][3];
        }
        rs0 += __shfl_xor_sync(0xffffffffu, rs0, 1);
        rs0 += __shfl_xor_sync(0xffffffffu, rs0, 2);
        rs1 += __shfl_xor_sync(0xffffffffu, rs1, 1);
        rs1 += __shfl_xor_sync(0xffffffffu, rs1, 2);
        mst0 = mn0; mst1 = mn1;
        lst0 = lst0 * es0 + rs0;
        lst1 = lst1 * es1 + rs1;

        // O = O*escale + P @ V   (P built directly from s registers)
#pragma unroll
        for (int nt = 0; nt < 16; nt++) {
            o[nt][0] *= es0; o[nt][1] *= es0;
            o[nt][2] *= es1; o[nt][3] *= es1;
        }
#pragma unroll
        for (int kk = 0; kk < 4; kk++) {       // key-dim blocks of 16
            uint32_t a[4];
            a[0] = packh2(s[2 * kk][0],     s[2 * kk][1]);
            a[1] = packh2(s[2 * kk][2],     s[2 * kk][3]);
            a[2] = packh2(s[2 * kk + 1][0], s[2 * kk + 1][1]);
            a[3] = packh2(s[2 * kk + 1][2], s[2 * kk + 1][3]);
#pragma unroll
            for (int ntp = 0; ntp < 8; ntp++) {
                uint32_t vb[4];
                LDSM4T(vb, vbase + kk * 4352 + ntp * 32 + vlane);
                mma16(o[ntp * 2],     a, vb[0], vb[1]);
                mma16(o[ntp * 2 + 1], a, vb[2], vb[3]);
            }
        }
    }
#undef LOADK
#undef LOADV

    // normalize + write ctx (half, for the dense GEMM)
    const float inv0 = 1.f / lst0, inv1 = 1.f / lst1;
#pragma unroll
    for (int nt = 0; nt < 16; nt++) {
        const int ccol = h * HDIM + nt * 8 + 2 * c;
        size_t r0 = ((size_t)((qb * 128 + m0 + g) * 2 + b)) * H_DIM + ccol;
        size_t r1 = ((size_t)((qb * 128 + m0 + g + 8) * 2 + b)) * H_DIM + ccol;
        *(__half2*)&g_ctx[r0] = __floats2half2_rn(o[nt][0] * inv0, o[nt][1] * inv0);
        *(__half2*)&g_ctx[r1] = __floats2half2_rn(o[nt][2] * inv1, o[nt][3] * inv1);
    }
}

// ---------------------------------------------------------------------------
extern "C" void kernel_launch(void* const* d_in, const int* in_sizes, int n_in,
                              void* d_out, int out_size)
{
    const float* hidden = (const float*)d_in[0];
    const float* rope   = (const float*)d_in[2];
    const float* Wqkv   = (const float*)d_in[3];
    const float* bqkv   = (const float*)d_in[4];
    const float* Wd     = (const float*)d_in[5];
    float* out = (float*)d_out;

    __half *mixed, *ctx, *hid, *wq, *wd;
    cudaGetSymbolAddress((void**)&mixed, g_mixed);
    cudaGetSymbolAddress((void**)&ctx,   g_ctx);
    cudaGetSymbolAddress((void**)&hid,   g_hid);
    cudaGetSymbolAddress((void**)&wq,    g_wq);
    cudaGetSymbolAddress((void**)&wd,    g_wd);

    cudaFuncSetAttribute(gemm_mma_kernel,
                         cudaFuncAttributeMaxDynamicSharedMemorySize, GEMM_SMEM);
    cudaFuncSetAttribute(flash_mma_kernel,
                         cudaFuncAttributeMaxDynamicSharedMemorySize, FLASH_SMEM);

    // fp16 pre-rounding (RNE) of GEMM inputs
    {
        int n4 = M_ROWS * H_DIM / 4;
        round_f16_kernel<<<n4 / 256, 256>>>((const float4*)hidden, (__half2*)hid, n4);
    }
    {
        int n4 = O_QKV * H_DIM / 4;
        round_f16_kernel<<<n4 / 256, 256>>>((const float4*)Wqkv, (__half2*)wq, n4);
    }
    {
        int n4 = H_DIM * H_DIM / 4;
        round_f16_kernel<<<n4 / 256, 256>>>((const float4*)Wd, (__half2*)wd, n4);
    }

    // 1) QKV projection + bias (half output -> flash consumes directly)
    gemm_mma_kernel<<<dim3(O_QKV / 128, M_ROWS / 128), 256, GEMM_SMEM>>>(
        hid, wq, bqkv, mixed, O_QKV, H_DIM, 1);

    // 2) RoPE (half in/out)
    const int total = S_LEN * B_SZ * (NHEADS + NGRP) * 32;
    rope_kernel<<<(total + 255) / 256, 256>>>(rope);

    // 3) flash attention (fp16, P in registers)
    flash_mma_kernel<<<dim3(S_LEN / 128, NHEADS, B_SZ), 256, FLASH_SMEM>>>();

    // 4) dense projection (fp32 output)
    gemm_mma_kernel<<<dim3(H_DIM / 128, M_ROWS / 128), 256, GEMM_SMEM>>>(
        ctx, wd, nullptr, out, H_DIM, H_DIM, 0);
}

// round 12
// speedup vs baseline: 1.1796x; 1.0354x over previous
#include <cuda_runtime.h>
#include <cuda_fp16.h>
#include <math.h>
#include <stdint.h>

#define S_LEN  2048
#define B_SZ   2
#define H_DIM  4096
#define NHEADS 32
#define NGRP   2
#define HDIM   128
#define O_QKV  4608
#define M_ROWS 4096

// ---------------- scratch (__device__ globals; allocation-free rule) --------
__device__ __half g_mixed[M_ROWS * O_QKV];
__device__ __half g_ctx[M_ROWS * H_DIM];
__device__ __half g_hid[M_ROWS * H_DIM];
__device__ __half g_wq[O_QKV * H_DIM];
__device__ __half g_wd[H_DIM * H_DIM];

// ---------------- helpers ----------------------------------------------------
__device__ __forceinline__ uint32_t smem_u32(const void* p) {
    uint32_t a;
    asm("{ .reg .u64 t; cvta.to.shared.u64 t, %1; cvt.u32.u64 %0, t; }" : "=r"(a) : "l"(p));
    return a;
}
__device__ __forceinline__ void cp_async16(uint32_t dst, const void* src) {
    asm volatile("cp.async.cg.shared.global [%0], [%1], 16;" :: "r"(dst), "l"(src));
}
__device__ __forceinline__ void cp_commit() {
    asm volatile("cp.async.commit_group;" ::: "memory");
}
template<int N> __device__ __forceinline__ void cp_wait() {
    asm volatile("cp.async.wait_group %0;" :: "n"(N) : "memory");
}
// D += A*B, m16n8k16 fp16 in / fp32 acc
__device__ __forceinline__ void mma16(float* d, const uint32_t* a, uint32_t b0, uint32_t b1) {
    asm volatile("mma.sync.aligned.m16n8k16.row.col.f32.f16.f16.f32 "
        "{%0,%1,%2,%3}, {%4,%5,%6,%7}, {%8,%9}, {%0,%1,%2,%3};"
        : "+f"(d[0]), "+f"(d[1]), "+f"(d[2]), "+f"(d[3])
        : "r"(a[0]), "r"(a[1]), "r"(a[2]), "r"(a[3]), "r"(b0), "r"(b1));
}
#define LDSM4(r, addr) \
    asm volatile("ldmatrix.sync.aligned.m8n8.x4.shared.b16 {%0,%1,%2,%3}, [%4];" \
        : "=r"((r)[0]), "=r"((r)[1]), "=r"((r)[2]), "=r"((r)[3]) : "r"(addr))
#define LDSM4T(r, addr) \
    asm volatile("ldmatrix.sync.aligned.m8n8.x4.trans.shared.b16 {%0,%1,%2,%3}, [%4];" \
        : "=r"((r)[0]), "=r"((r)[1]), "=r"((r)[2]), "=r"((r)[3]) : "r"(addr))

__device__ __forceinline__ uint32_t h2u(__half2 h) { return *reinterpret_cast<uint32_t*>(&h); }
__device__ __forceinline__ uint32_t packh2(float lo, float hi) {
    __half2 h = __floats2half2_rn(lo, hi);        // low 16 bits = lo
    return *reinterpret_cast<uint32_t*>(&h);
}

// ---------------- f32 -> f16 rounding pass ----------------------------------
__global__ __launch_bounds__(256) void round_f16_kernel(
    const float4* __restrict__ in, __half2* __restrict__ out, int n4)
{
    int i = blockIdx.x * blockDim.x + threadIdx.x;
    if (i >= n4) return;
    float4 v = in[i];
    out[2 * i]     = __floats2half2_rn(v.x, v.y);
    out[2 * i + 1] = __floats2half2_rn(v.z, v.w);
}

// ---------------- fp16 mma GEMM: C[M,N] = A[M,K] @ W[N,K]^T (+bias) ---------
// 512 thr (16 warps, warp grid 2Mx8N, warp tile 64x32), CTA 128x256.
// K-chunk 64 halves, 4-stage cp.async (3 chunks in flight), ldmatrix frags.
// Optional fused RoPE in the epilogue (QKV path).
// smem rows padded to 72 halves (144 B).
#define A_STG_B (128 * 144)            // 18432
#define B_STG_B (256 * 144)            // 36864
#define STG_B   (A_STG_B + B_STG_B)    // 55296
#define GEMM_SMEM (4 * STG_B)          // 221184

__global__ __launch_bounds__(512, 1) void gemm_mma_kernel(
    const __half* __restrict__ A, const __half* __restrict__ W,
    const float* __restrict__ bias, void* __restrict__ Cv,
    const float* __restrict__ rope,    // non-null => fused RoPE (QKV path)
    int N, int K, int out_half)
{
    extern __shared__ char smc[];
    const uint32_t sb = smem_u32(smc);

    const int tid = threadIdx.x;
    const int wid = tid >> 5, lid = tid & 31;
    const int g = lid >> 2, c = lid & 3;
    const int m4 = lid >> 3, r8 = lid & 7;
    const int m0 = (wid & 1) * 64, n0 = (wid >> 1) * 32;
    const int row0 = blockIdx.y * 128;
    const int col0 = blockIdx.x * 256;

    // ldmatrix per-lane byte offsets
    const uint32_t laneA = ((m4 & 1) * 8 + r8) * 144 + (m4 >> 1) * 16;
    const uint32_t laneB = ((m4 >> 1) * 8 + r8) * 144 + (m4 & 1) * 16;

    float acc[4][4][4];
#pragma unroll
    for (int i = 0; i < 4; i++)
#pragma unroll
        for (int j = 0; j < 4; j++)
#pragma unroll
            for (int k = 0; k < 4; k++) acc[i][j][k] = 0.f;

    const int nchunk = K / 64;
    const int arow = tid >> 2;                 // 0..127
    const int aseg = (tid & 3) * 2;            // 0,2,4,6 (+1)
    const int brow = tid >> 1;                 // 0..255
    const int bseg = (tid & 1) * 4;            // 0 or 4 (+0..3)

#define LOADCH(ch, st) do {                                                    \
        const __half* _a = A + (size_t)(row0 + arow) * K + (ch) * 64;          \
        const __half* _b = W + (size_t)(col0 + brow) * K + (ch) * 64;          \
        uint32_t _da = sb + (st) * STG_B + arow * 144;                         \
        uint32_t _db = sb + (st) * STG_B + A_STG_B + brow * 144;               \
        cp_async16(_da + (aseg + 0) * 16, _a + (aseg + 0) * 8);                \
        cp_async16(_da + (aseg + 1) * 16, _a + (aseg + 1) * 8);                \
        cp_async16(_db + (bseg + 0) * 16, _b + (bseg + 0) * 8);                \
        cp_async16(_db + (bseg + 1) * 16, _b + (bseg + 1) * 8);                \
        cp_async16(_db + (bseg + 2) * 16, _b + (bseg + 2) * 8);                \
        cp_async16(_db + (bseg + 3) * 16, _b + (bseg + 3) * 8);                \
        cp_commit();                                                           \
    } while (0)

    LOADCH(0, 0);
    LOADCH(1, 1);
    LOADCH(2, 2);

    for (int i = 0; i < nchunk; i++) {
        if (i + 1 < nchunk) cp_wait<2>(); else cp_wait<0>();
        __syncthreads();
        if (i + 3 < nchunk) LOADCH(i + 3, (i + 3) & 3);

        const uint32_t stA = sb + (i & 3) * STG_B;
        const uint32_t stB = stA + A_STG_B;
#pragma unroll
        for (int kk = 0; kk < 4; kk++) {
            uint32_t af[4][4], bf[2][4];
#pragma unroll
            for (int mt = 0; mt < 4; mt++)
                LDSM4(af[mt], stA + (m0 + mt * 16) * 144 + kk * 32 + laneA);
#pragma unroll
            for (int np = 0; np < 2; np++)
                LDSM4(bf[np], stB + (n0 + np * 16) * 144 + kk * 32 + laneB);
#pragma unroll
            for (int mt = 0; mt < 4; mt++)
#pragma unroll
                for (int np = 0; np < 2; np++) {
                    mma16(acc[mt][np * 2],     af[mt], bf[np][0], bf[np][1]);
                    mma16(acc[mt][np * 2 + 1], af[mt], bf[np][2], bf[np][3]);
                }
        }
    }
#undef LOADCH

    // epilogue (+bias, optional fused RoPE, fp16 or fp32 output)
#pragma unroll
    for (int mt = 0; mt < 4; mt++) {
#pragma unroll
        for (int nt = 0; nt < 4; nt++) {
            const int rr = row0 + m0 + mt * 16 + g;
            const int cc = col0 + n0 + nt * 8 + 2 * c;
            float b0 = bias ? bias[cc] : 0.f;
            float b1 = bias ? bias[cc + 1] : 0.f;
            float v00 = acc[mt][nt][0] + b0, v01 = acc[mt][nt][1] + b1;
            float v10 = acc[mt][nt][2] + b0, v11 = acc[mt][nt][3] + b1;
            if (rope) {
                const int d = cc & 127;            // even
                if (cc < 4352 && d < 64) {         // Q heads + K heads, rot dims
                    const int s0 = rr >> 1, s1 = (rr + 8) >> 1;
                    float c0 = rope[s0 * 64 + d], sn0 = rope[s0 * 64 + d + 1];
                    float c1 = rope[s1 * 64 + d], sn1 = rope[s1 * 64 + d + 1];
                    float t00 = v00 * c0 - v01 * sn0;
                    float t01 = v01 * c0 + v00 * sn0;
                    float t10 = v10 * c1 - v11 * sn1;
                    float t11 = v11 * c1 + v10 * sn1;
                    v00 = t00; v01 = t01; v10 = t10; v11 = t11;
                }
            }
            if (out_half) {
                __half* C = (__half*)Cv;
                *(__half2*)&C[(size_t)rr * N + cc]       = __floats2half2_rn(v00, v01);
                *(__half2*)&C[(size_t)(rr + 8) * N + cc] = __floats2half2_rn(v10, v11);
            } else {
                float* C = (float*)Cv;
                *(float2*)&C[(size_t)rr * N + cc]       = make_float2(v00, v01);
                *(float2*)&C[(size_t)(rr + 8) * N + cc] = make_float2(v10, v11);
            }
        }
    }
}

// ---------------- flash attention fp16, BQ=128, P-in-registers --------------
// 256 thr / 8 warps; warp w owns Q rows [w*16, w*16+16).
// K/V double-buffered via cp.async; V B-frags via ldmatrix.trans.
// smem: K0,K1,V0,V1 each 64 rows x 272 B (136-half stride) = 17408 B.
#define KB0 0
#define KB1 17408
#define VB0 34816
#define VB1 52224
#define FLASH_SMEM 69632

__global__ __launch_bounds__(256, 1) void flash_mma_kernel()
{
    extern __shared__ char smf[];
    const uint32_t sbase = smem_u32(smf);

    const int qb = blockIdx.x, h = blockIdx.y, b = blockIdx.z;
    const int grp = h >> 4;
    const int tid = threadIdx.x, wid = tid >> 5, lid = tid & 31;
    const int g = lid >> 2, c = lid & 3;
    const int m4 = lid >> 3, r8 = lid & 7;
    const int m0 = wid * 16;
    const float scale = 0.08838834764831843f;

    // ldmatrix.trans per-lane byte offset into a V buffer
    const uint32_t vlane = ((m4 & 1) * 8 + r8) * 272 + (m4 >> 1) * 16;

    // K/V tile loaders: 64 rows x 256 B = 1024 segs (4 per thread)
#define LOADK(kb, p) do {                                                       \
        _Pragma("unroll")                                                       \
        for (int _s = 0; _s < 4; _s++) {                                        \
            int _ln = tid + _s * 256;                                           \
            int _r = _ln >> 4, _c = _ln & 15;                                   \
            cp_async16(sbase + ((p) ? KB1 : KB0) + _r * 272 + _c * 16,          \
                &g_mixed[((size_t)(((kb) * 64 + _r) * 2 + b)) * O_QKV           \
                         + 4096 + grp * HDIM + _c * 8]);                        \
        } } while (0)
#define LOADV(kb, p) do {                                                       \
        _Pragma("unroll")                                                       \
        for (int _s = 0; _s < 4; _s++) {                                        \
            int _ln = tid + _s * 256;                                           \
            int _r = _ln >> 4, _c = _ln & 15;                                   \
            cp_async16(sbase + ((p) ? VB1 : VB0) + _r * 272 + _c * 16,          \
                &g_mixed[((size_t)(((kb) * 64 + _r) * 2 + b)) * O_QKV           \
                         + 4352 + grp * HDIM + _c * 8]);                        \
        } } while (0)

    // ---- stage Q (128 rows x 16 segs) through K0/V0, extract frags ----------
#pragma unroll
    for (int s = 0; s < 8; s++) {
        int ln = tid + s * 256;            // 0..2047
        int r = ln >> 4, cseg = ln & 15;
        uint32_t dst = (r < 64) ? (sbase + KB0 + r * 272 + cseg * 16)
                                : (sbase + VB0 + (r - 64) * 272 + cseg * 16);
        cp_async16(dst, &g_mixed[((size_t)((qb * 128 + r) * 2 + b)) * O_QKV
                                 + h * HDIM + cseg * 8]);
    }
    cp_commit();
    cp_wait<0>();
    __syncthreads();

    uint32_t qf[8][4];
    {
        const __half2* q2 = (const __half2*)(smf + ((wid < 4) ? KB0 : VB0));
        const int rl = (m0 & 63) + g;
#pragma unroll
        for (int kk = 0; kk < 8; kk++) {
            qf[kk][0] = h2u(q2[rl * 68 + kk * 8 + c]);
            qf[kk][1] = h2u(q2[(rl + 8) * 68 + kk * 8 + c]);
            qf[kk][2] = h2u(q2[rl * 68 + kk * 8 + c + 4]);
            qf[kk][3] = h2u(q2[(rl + 8) * 68 + kk * 8 + c + 4]);
        }
    }
    __syncthreads();   // all warps done reading before K0/V0 reload

    float o[16][4];
#pragma unroll
    for (int nt = 0; nt < 16; nt++)
#pragma unroll
        for (int j = 0; j < 4; j++) o[nt][j] = 0.f;
    float mst0 = -INFINITY, mst1 = -INFINITY, lst0 = 0.f, lst1 = 0.f;

    const int nkb = 2 * qb + 2;
    LOADK(0, 0); LOADV(0, 0); cp_commit();

    for (int kb = 0; kb < nkb; kb++) {
        const int p = kb & 1;
        cp_wait<0>();
        __syncthreads();
        if (kb + 1 < nkb) { LOADK(kb + 1, p ^ 1); LOADV(kb + 1, p ^ 1); cp_commit(); }

        const __half2* k2 = (const __half2*)(smf + (p ? KB1 : KB0));
        const uint32_t vbase = sbase + (p ? VB1 : VB0);

        // S = Q @ K^T  (16 rows x 64 cols per warp)
        float s[8][4];
#pragma unroll
        for (int nt = 0; nt < 8; nt++)
#pragma unroll
            for (int j = 0; j < 4; j++) s[nt][j] = 0.f;
#pragma unroll
        for (int kk = 0; kk < 8; kk++) {
#pragma unroll
            for (int nt = 0; nt < 8; nt++) {
                uint32_t b0 = h2u(k2[(nt * 8 + g) * 68 + kk * 8 + c]);
                uint32_t b1 = h2u(k2[(nt * 8 + g) * 68 + kk * 8 + c + 4]);
                mma16(s[nt], qf[kk], b0, b1);
            }
        }

        if (kb >= 2 * qb) {        // causal mask (diagonal region)
            const int r0 = qb * 128 + m0 + g, r1 = r0 + 8;
            const int cb = kb * 64;
#pragma unroll
            for (int nt = 0; nt < 8; nt++) {
                const int n = cb + nt * 8 + 2 * c;
                if (n > r0)     s[nt][0] = -1e30f;
                if (n + 1 > r0) s[nt][1] = -1e30f;
                if (n > r1)     s[nt][2] = -1e30f;
                if (n + 1 > r1) s[nt][3] = -1e30f;
            }
        }

        // online softmax, scale folded: p = exp((s - m) * scale)
        float rm0 = -INFINITY, rm1 = -INFINITY;
#pragma unroll
        for (int nt = 0; nt < 8; nt++) {
            rm0 = fmaxf(rm0, fmaxf(s[nt][0], s[nt][1]));
            rm1 = fmaxf(rm1, fmaxf(s[nt][2], s[nt][3]));
        }
        rm0 = fmaxf(rm0, __shfl_xor_sync(0xffffffffu, rm0, 1));
        rm0 = fmaxf(rm0, __shfl_xor_sync(0xffffffffu, rm0, 2));
        rm1 = fmaxf(rm1, __shfl_xor_sync(0xffffffffu, rm1, 1));
        rm1 = fmaxf(rm1, __shfl_xor_sync(0xffffffffu, rm1, 2));
        const float mn0 = fmaxf(mst0, rm0);
        const float mn1 = fmaxf(mst1, rm1);
        const float es0 = __expf((mst0 - mn0) * scale);
        const float es1 = __expf((mst1 - mn1) * scale);
        float rs0 = 0.f, rs1 = 0.f;
#pragma unroll
        for (int nt = 0; nt < 8; nt++) {
            s[nt][0] = __expf((s[nt][0] - mn0) * scale);
            s[nt][1] = __expf((s[nt][1] - mn0) * scale);
            s[nt][2] = __expf((s[nt][2] - mn1) * scale);
            s[nt][3] = __expf((s[nt][3] - mn1) * scale);
            rs0 += s[nt][0] + s[nt][1];
            rs1 += s[nt][2] + s[nt][3];
        }
        rs0 += __shfl_xor_sync(0xffffffffu, rs0, 1);
        rs0 += __shfl_xor_sync(0xffffffffu, rs0, 2);
        rs1 += __shfl_xor_sync(0xffffffffu, rs1, 1);
        rs1 += __shfl_xor_sync(0xffffffffu, rs1, 2);
        mst0 = mn0; mst1 = mn1;
        lst0 = lst0 * es0 + rs0;
        lst1 = lst1 * es1 + rs1;

        // O = O*escale + P @ V   (P built directly from s registers)
#pragma unroll
        for (int nt = 0; nt < 16; nt++) {
            o[nt][0] *= es0; o[nt][1] *= es0;
            o[nt][2] *= es1; o[nt][3] *= es1;
        }
#pragma unroll
        for (int kk = 0; kk < 4; kk++) {       // key-dim blocks of 16
            uint32_t a[4];
            a[0] = packh2(s[2 * kk][0],     s[2 * kk][1]);
            a[1] = packh2(s[2 * kk][2],     s[2 * kk][3]);
            a[2] = packh2(s[2 * kk + 1][0], s[2 * kk + 1][1]);
            a[3] = packh2(s[2 * kk + 1][2], s[2 * kk + 1][3]);
#pragma unroll
            for (int ntp = 0; ntp < 8; ntp++) {
                uint32_t vb[4];
                LDSM4T(vb, vbase + kk * 4352 + ntp * 32 + vlane);
                mma16(o[ntp * 2],     a, vb[0], vb[1]);
                mma16(o[ntp * 2 + 1], a, vb[2], vb[3]);
            }
        }
    }
#undef LOADK
#undef LOADV

    // normalize + write ctx (half, for the dense GEMM)
    const float inv0 = 1.f / lst0, inv1 = 1.f / lst1;
#pragma unroll
    for (int nt = 0; nt < 16; nt++) {
        const int ccol = h * HDIM + nt * 8 + 2 * c;
        size_t r0 = ((size_t)((qb * 128 + m0 + g) * 2 + b)) * H_DIM + ccol;
        size_t r1 = ((size_t)((qb * 128 + m0 + g + 8) * 2 + b)) * H_DIM + ccol;
        *(__half2*)&g_ctx[r0] = __floats2half2_rn(o[nt][0] * inv0, o[nt][1] * inv0);
        *(__half2*)&g_ctx[r1] = __floats2half2_rn(o[nt][2] * inv1, o[nt][3] * inv1);
    }
}

// ---------------------------------------------------------------------------
extern "C" void kernel_launch(void* const* d_in, const int* in_sizes, int n_in,
                              void* d_out, int out_size)
{
    const float* hidden = (const float*)d_in[0];
    const float* rope   = (const float*)d_in[2];
    const float* Wqkv   = (const float*)d_in[3];
    const float* bqkv   = (const float*)d_in[4];
    const float* Wd     = (const float*)d_in[5];
    float* out = (float*)d_out;

    __half *mixed, *ctx, *hid, *wq, *wd;
    cudaGetSymbolAddress((void**)&mixed, g_mixed);
    cudaGetSymbolAddress((void**)&ctx,   g_ctx);
    cudaGetSymbolAddress((void**)&hid,   g_hid);
    cudaGetSymbolAddress((void**)&wq,    g_wq);
    cudaGetSymbolAddress((void**)&wd,    g_wd);

    cudaFuncSetAttribute(gemm_mma_kernel,
                         cudaFuncAttributeMaxDynamicSharedMemorySize, GEMM_SMEM);
    cudaFuncSetAttribute(flash_mma_kernel,
                         cudaFuncAttributeMaxDynamicSharedMemorySize, FLASH_SMEM);

    // fp16 pre-rounding (RNE) of GEMM inputs
    {
        int n4 = M_ROWS * H_DIM / 4;
        round_f16_kernel<<<n4 / 256, 256>>>((const float4*)hidden, (__half2*)hid, n4);
    }
    {
        int n4 = O_QKV * H_DIM / 4;
        round_f16_kernel<<<n4 / 256, 256>>>((const float4*)Wqkv, (__half2*)wq, n4);
    }
    {
        int n4 = H_DIM * H_DIM / 4;
        round_f16_kernel<<<n4 / 256, 256>>>((const float4*)Wd, (__half2*)wd, n4);
    }

    // 1) QKV projection + bias + fused RoPE (half output)
    gemm_mma_kernel<<<dim3(O_QKV / 256, M_ROWS / 128), 512, GEMM_SMEM>>>(
        hid, wq, bqkv, mixed, rope, O_QKV, H_DIM, 1);

    // 2) flash attention (fp16, P in registers)
    flash_mma_kernel<<<dim3(S_LEN / 128, NHEADS, B_SZ), 256, FLASH_SMEM>>>();

    // 3) dense projection (fp32 output, no rope)
    gemm_mma_kernel<<<dim3(H_DIM / 256, M_ROWS / 128), 512, GEMM_SMEM>>>(
        ctx, wd, nullptr, out, nullptr, H_DIM, H_DIM, 0);
}

// round 13
// speedup vs baseline: 1.1865x; 1.0058x over previous
#include <cuda_runtime.h>
#include <cuda_fp16.h>
#include <math.h>
#include <stdint.h>

#define S_LEN  2048
#define B_SZ   2
#define H_DIM  4096
#define NHEADS 32
#define NGRP   2
#define HDIM   128
#define O_QKV  4608
#define M_ROWS 4096

// ---------------- scratch (__device__ globals; allocation-free rule) --------
__device__ __half g_mixed[M_ROWS * O_QKV];
__device__ __half g_ctx[M_ROWS * H_DIM];
__device__ __half g_hid[M_ROWS * H_DIM];
__device__ __half g_wq[O_QKV * H_DIM];
__device__ __half g_wd[H_DIM * H_DIM];

// ---------------- helpers ----------------------------------------------------
__device__ __forceinline__ uint32_t smem_u32(const void* p) {
    uint32_t a;
    asm("{ .reg .u64 t; cvta.to.shared.u64 t, %1; cvt.u32.u64 %0, t; }" : "=r"(a) : "l"(p));
    return a;
}
__device__ __forceinline__ void cp_async16(uint32_t dst, const void* src) {
    asm volatile("cp.async.cg.shared.global [%0], [%1], 16;" :: "r"(dst), "l"(src));
}
__device__ __forceinline__ void cp_commit() {
    asm volatile("cp.async.commit_group;" ::: "memory");
}
template<int N> __device__ __forceinline__ void cp_wait() {
    asm volatile("cp.async.wait_group %0;" :: "n"(N) : "memory");
}
// D += A*B, m16n8k16 fp16 in / fp32 acc
__device__ __forceinline__ void mma16(float* d, const uint32_t* a, uint32_t b0, uint32_t b1) {
    asm volatile("mma.sync.aligned.m16n8k16.row.col.f32.f16.f16.f32 "
        "{%0,%1,%2,%3}, {%4,%5,%6,%7}, {%8,%9}, {%0,%1,%2,%3};"
        : "+f"(d[0]), "+f"(d[1]), "+f"(d[2]), "+f"(d[3])
        : "r"(a[0]), "r"(a[1]), "r"(a[2]), "r"(a[3]), "r"(b0), "r"(b1));
}
#define LDSM4(r, addr) \
    asm volatile("ldmatrix.sync.aligned.m8n8.x4.shared.b16 {%0,%1,%2,%3}, [%4];" \
        : "=r"((r)[0]), "=r"((r)[1]), "=r"((r)[2]), "=r"((r)[3]) : "r"(addr))
#define LDSM4T(r, addr) \
    asm volatile("ldmatrix.sync.aligned.m8n8.x4.trans.shared.b16 {%0,%1,%2,%3}, [%4];" \
        : "=r"((r)[0]), "=r"((r)[1]), "=r"((r)[2]), "=r"((r)[3]) : "r"(addr))

__device__ __forceinline__ uint32_t h2u(__half2 h) { return *reinterpret_cast<uint32_t*>(&h); }
__device__ __forceinline__ uint32_t packh2(float lo, float hi) {
    __half2 h = __floats2half2_rn(lo, hi);        // low 16 bits = lo
    return *reinterpret_cast<uint32_t*>(&h);
}

// ---------------- fused f32 -> f16 rounding pass (all three tensors) --------
__global__ __launch_bounds__(256) void round_all_kernel(
    const float4* __restrict__ in0, __half2* __restrict__ out0, int n0,
    const float4* __restrict__ in1, __half2* __restrict__ out1, int n1,
    const float4* __restrict__ in2, __half2* __restrict__ out2, int n2)
{
    int i = blockIdx.x * blockDim.x + threadIdx.x;
    const float4* in; __half2* out; int j = i;
    if (j < n0)            { in = in0; out = out0; }
    else if ((j -= n0) < n1) { in = in1; out = out1; }
    else if ((j -= n1) < n2) { in = in2; out = out2; }
    else return;
    float4 v = in[j];
    out[2 * j]     = __floats2half2_rn(v.x, v.y);
    out[2 * j + 1] = __floats2half2_rn(v.z, v.w);
}

// ---------------- fp16 mma GEMM: C[M,N] = A[M,K] @ W[N,K]^T (+bias) ---------
// 512 thr (16 warps, warp grid 2Mx8N, warp tile 64x32), CTA 128x256.
// K-chunk 64 halves, 4-stage cp.async (3 chunks in flight), ldmatrix frags.
// Optional fused RoPE in the epilogue (QKV path).
#define A_STG_B (128 * 144)            // 18432
#define B_STG_B (256 * 144)            // 36864
#define STG_B   (A_STG_B + B_STG_B)    // 55296
#define GEMM_SMEM (4 * STG_B)          // 221184

__global__ __launch_bounds__(512, 1) void gemm_mma_kernel(
    const __half* __restrict__ A, const __half* __restrict__ W,
    const float* __restrict__ bias, void* __restrict__ Cv,
    const float* __restrict__ rope,
    int N, int K, int out_half)
{
    extern __shared__ char smc[];
    const uint32_t sb = smem_u32(smc);

    const int tid = threadIdx.x;
    const int wid = tid >> 5, lid = tid & 31;
    const int g = lid >> 2, c = lid & 3;
    const int m4 = lid >> 3, r8 = lid & 7;
    const int m0 = (wid & 1) * 64, n0 = (wid >> 1) * 32;
    const int row0 = blockIdx.y * 128;
    const int col0 = blockIdx.x * 256;

    const uint32_t laneA = ((m4 & 1) * 8 + r8) * 144 + (m4 >> 1) * 16;
    const uint32_t laneB = ((m4 >> 1) * 8 + r8) * 144 + (m4 & 1) * 16;

    float acc[4][4][4];
#pragma unroll
    for (int i = 0; i < 4; i++)
#pragma unroll
        for (int j = 0; j < 4; j++)
#pragma unroll
            for (int k = 0; k < 4; k++) acc[i][j][k] = 0.f;

    const int nchunk = K / 64;
    const int arow = tid >> 2;
    const int aseg = (tid & 3) * 2;
    const int brow = tid >> 1;
    const int bseg = (tid & 1) * 4;

#define LOADCH(ch, st) do {                                                    \
        const __half* _a = A + (size_t)(row0 + arow) * K + (ch) * 64;          \
        const __half* _b = W + (size_t)(col0 + brow) * K + (ch) * 64;          \
        uint32_t _da = sb + (st) * STG_B + arow * 144;                         \
        uint32_t _db = sb + (st) * STG_B + A_STG_B + brow * 144;               \
        cp_async16(_da + (aseg + 0) * 16, _a + (aseg + 0) * 8);                \
        cp_async16(_da + (aseg + 1) * 16, _a + (aseg + 1) * 8);                \
        cp_async16(_db + (bseg + 0) * 16, _b + (bseg + 0) * 8);                \
        cp_async16(_db + (bseg + 1) * 16, _b + (bseg + 1) * 8);                \
        cp_async16(_db + (bseg + 2) * 16, _b + (bseg + 2) * 8);                \
        cp_async16(_db + (bseg + 3) * 16, _b + (bseg + 3) * 8);                \
        cp_commit();                                                           \
    } while (0)

    LOADCH(0, 0);
    LOADCH(1, 1);
    LOADCH(2, 2);

    for (int i = 0; i < nchunk; i++) {
        if (i + 1 < nchunk) cp_wait<2>(); else cp_wait<0>();
        __syncthreads();
        if (i + 3 < nchunk) LOADCH(i + 3, (i + 3) & 3);

        const uint32_t stA = sb + (i & 3) * STG_B;
        const uint32_t stB = stA + A_STG_B;
#pragma unroll
        for (int kk = 0; kk < 4; kk++) {
            uint32_t af[4][4], bf[2][4];
#pragma unroll
            for (int mt = 0; mt < 4; mt++)
                LDSM4(af[mt], stA + (m0 + mt * 16) * 144 + kk * 32 + laneA);
#pragma unroll
            for (int np = 0; np < 2; np++)
                LDSM4(bf[np], stB + (n0 + np * 16) * 144 + kk * 32 + laneB);
#pragma unroll
            for (int mt = 0; mt < 4; mt++)
#pragma unroll
                for (int np = 0; np < 2; np++) {
                    mma16(acc[mt][np * 2],     af[mt], bf[np][0], bf[np][1]);
                    mma16(acc[mt][np * 2 + 1], af[mt], bf[np][2], bf[np][3]);
                }
        }
    }
#undef LOADCH

    // epilogue (+bias, optional fused RoPE, fp16 or fp32 output)
#pragma unroll
    for (int mt = 0; mt < 4; mt++) {
#pragma unroll
        for (int nt = 0; nt < 4; nt++) {
            const int rr = row0 + m0 + mt * 16 + g;
            const int cc = col0 + n0 + nt * 8 + 2 * c;
            float b0 = bias ? bias[cc] : 0.f;
            float b1 = bias ? bias[cc + 1] : 0.f;
            float v00 = acc[mt][nt][0] + b0, v01 = acc[mt][nt][1] + b1;
            float v10 = acc[mt][nt][2] + b0, v11 = acc[mt][nt][3] + b1;
            if (rope) {
                const int d = cc & 127;
                if (cc < 4352 && d < 64) {
                    const int s0 = rr >> 1, s1 = (rr + 8) >> 1;
                    float c0 = rope[s0 * 64 + d], sn0 = rope[s0 * 64 + d + 1];
                    float c1 = rope[s1 * 64 + d], sn1 = rope[s1 * 64 + d + 1];
                    float t00 = v00 * c0 - v01 * sn0;
                    float t01 = v01 * c0 + v00 * sn0;
                    float t10 = v10 * c1 - v11 * sn1;
                    float t11 = v11 * c1 + v10 * sn1;
                    v00 = t00; v01 = t01; v10 = t10; v11 = t11;
                }
            }
            if (out_half) {
                __half* C = (__half*)Cv;
                *(__half2*)&C[(size_t)rr * N + cc]       = __floats2half2_rn(v00, v01);
                *(__half2*)&C[(size_t)(rr + 8) * N + cc] = __floats2half2_rn(v10, v11);
            } else {
                float* C = (float*)Cv;
                *(float2*)&C[(size_t)rr * N + cc]       = make_float2(v00, v01);
                *(float2*)&C[(size_t)(rr + 8) * N + cc] = make_float2(v10, v11);
            }
        }
    }
}

// ---------------- flash attention fp16, BQ=128, P-in-registers --------------
// 256 thr / 8 warps; warp w owns Q rows [w*16, w*16+16).
// K/V double-buffered via cp.async; V B-frags via ldmatrix.trans.
// qb launched in DESCENDING work order for load balance.
// smem: K0,K1,V0,V1 each 64 rows x 272 B (136-half stride) = 17408 B.
#define KB0 0
#define KB1 17408
#define VB0 34816
#define VB1 52224
#define FLASH_SMEM 69632

__global__ __launch_bounds__(256, 1) void flash_mma_kernel()
{
    extern __shared__ char smf[];
    const uint32_t sbase = smem_u32(smf);

    const int qb = gridDim.x - 1 - blockIdx.x;   // long CTAs first
    const int h = blockIdx.y, b = blockIdx.z;
    const int grp = h >> 4;
    const int tid = threadIdx.x, wid = tid >> 5, lid = tid & 31;
    const int g = lid >> 2, c = lid & 3;
    const int m4 = lid >> 3, r8 = lid & 7;
    const int m0 = wid * 16;
    const float scale = 0.08838834764831843f;

    const uint32_t vlane = ((m4 & 1) * 8 + r8) * 272 + (m4 >> 1) * 16;

#define LOADK(kb, p) do {                                                       \
        _Pragma("unroll")                                                       \
        for (int _s = 0; _s < 4; _s++) {                                        \
            int _ln = tid + _s * 256;                                           \
            int _r = _ln >> 4, _c = _ln & 15;                                   \
            cp_async16(sbase + ((p) ? KB1 : KB0) + _r * 272 + _c * 16,          \
                &g_mixed[((size_t)(((kb) * 64 + _r) * 2 + b)) * O_QKV           \
                         + 4096 + grp * HDIM + _c * 8]);                        \
        } } while (0)
#define LOADV(kb, p) do {                                                       \
        _Pragma("unroll")                                                       \
        for (int _s = 0; _s < 4; _s++) {                                        \
            int _ln = tid + _s * 256;                                           \
            int _r = _ln >> 4, _c = _ln & 15;                                   \
            cp_async16(sbase + ((p) ? VB1 : VB0) + _r * 272 + _c * 16,          \
                &g_mixed[((size_t)(((kb) * 64 + _r) * 2 + b)) * O_QKV           \
                         + 4352 + grp * HDIM + _c * 8]);                        \
        } } while (0)

    // ---- stage Q into KB1/VB1 AND issue kb=0 K/V into KB0/VB0: one group ----
#pragma unroll
    for (int s = 0; s < 8; s++) {
        int ln = tid + s * 256;            // 0..2047
        int r = ln >> 4, cseg = ln & 15;
        uint32_t dst = (r < 64) ? (sbase + KB1 + r * 272 + cseg * 16)
                                : (sbase + VB1 + (r - 64) * 272 + cseg * 16);
        cp_async16(dst, &g_mixed[((size_t)((qb * 128 + r) * 2 + b)) * O_QKV
                                 + h * HDIM + cseg * 8]);
    }
    LOADK(0, 0); LOADV(0, 0);
    cp_commit();
    cp_wait<0>();
    __syncthreads();

    uint32_t qf[8][4];
    {
        const __half2* q2 = (const __half2*)(smf + ((wid < 4) ? KB1 : VB1));
        const int rl = (m0 & 63) + g;
#pragma unroll
        for (int kk = 0; kk < 8; kk++) {
            qf[kk][0] = h2u(q2[rl * 68 + kk * 8 + c]);
            qf[kk][1] = h2u(q2[(rl + 8) * 68 + kk * 8 + c]);
            qf[kk][2] = h2u(q2[rl * 68 + kk * 8 + c + 4]);
            qf[kk][3] = h2u(q2[(rl + 8) * 68 + kk * 8 + c + 4]);
        }
    }
    __syncthreads();   // all warps done reading KB1/VB1 before kb=1 load

    float o[16][4];
#pragma unroll
    for (int nt = 0; nt < 16; nt++)
#pragma unroll
        for (int j = 0; j < 4; j++) o[nt][j] = 0.f;
    float mst0 = -INFINITY, mst1 = -INFINITY, lst0 = 0.f, lst1 = 0.f;

    const int nkb = 2 * qb + 2;

    for (int kb = 0; kb < nkb; kb++) {
        const int p = kb & 1;
        cp_wait<0>();
        __syncthreads();
        if (kb + 1 < nkb) { LOADK(kb + 1, p ^ 1); LOADV(kb + 1, p ^ 1); cp_commit(); }

        const __half2* k2 = (const __half2*)(smf + (p ? KB1 : KB0));
        const uint32_t vbase = sbase + (p ? VB1 : VB0);

        // S = Q @ K^T
        float s[8][4];
#pragma unroll
        for (int nt = 0; nt < 8; nt++)
#pragma unroll
            for (int j = 0; j < 4; j++) s[nt][j] = 0.f;
#pragma unroll
        for (int kk = 0; kk < 8; kk++) {
#pragma unroll
            for (int nt = 0; nt < 8; nt++) {
                uint32_t b0 = h2u(k2[(nt * 8 + g) * 68 + kk * 8 + c]);
                uint32_t b1 = h2u(k2[(nt * 8 + g) * 68 + kk * 8 + c + 4]);
                mma16(s[nt], qf[kk], b0, b1);
            }
        }

        if (kb >= 2 * qb) {        // causal mask (diagonal region)
            const int r0 = qb * 128 + m0 + g, r1 = r0 + 8;
            const int cb = kb * 64;
#pragma unroll
            for (int nt = 0; nt < 8; nt++) {
                const int n = cb + nt * 8 + 2 * c;
                if (n > r0)     s[nt][0] = -1e30f;
                if (n + 1 > r0) s[nt][1] = -1e30f;
                if (n > r1)     s[nt][2] = -1e30f;
                if (n + 1 > r1) s[nt][3] = -1e30f;
            }
        }

        // online softmax, scale folded
        float rm0 = -INFINITY, rm1 = -INFINITY;
#pragma unroll
        for (int nt = 0; nt < 8; nt++) {
            rm0 = fmaxf(rm0, fmaxf(s[nt][0], s[nt][1]));
            rm1 = fmaxf(rm1, fmaxf(s[nt][2], s[nt][3]));
        }
        rm0 = fmaxf(rm0, __shfl_xor_sync(0xffffffffu, rm0, 1));
        rm0 = fmaxf(rm0, __shfl_xor_sync(0xffffffffu, rm0, 2));
        rm1 = fmaxf(rm1, __shfl_xor_sync(0xffffffffu, rm1, 1));
        rm1 = fmaxf(rm1, __shfl_xor_sync(0xffffffffu, rm1, 2));
        const float mn0 = fmaxf(mst0, rm0);
        const float mn1 = fmaxf(mst1, rm1);
        const float es0 = __expf((mst0 - mn0) * scale);
        const float es1 = __expf((mst1 - mn1) * scale);
        float rs0 = 0.f, rs1 = 0.f;
#pragma unroll
        for (int nt = 0; nt < 8; nt++) {
            s[nt][0] = __expf((s[nt][0] - mn0) * scale);
            s[nt][1] = __expf((s[nt][1] - mn0) * scale);
            s[nt][2] = __expf((s[nt][2] - mn1) * scale);
            s[nt][3] = __expf((s[nt][3] - mn1) * scale);
            rs0 += s[nt][0] + s[nt][1];
            rs1 += s[nt][2] + s[nt][3];
        }
        rs0 += __shfl_xor_sync(0xffffffffu, rs0, 1);
        rs0 += __shfl_xor_sync(0xffffffffu, rs0, 2);
        rs1 += __shfl_xor_sync(0xffffffffu, rs1, 1);
        rs1 += __shfl_xor_sync(0xffffffffu, rs1, 2);
        mst0 = mn0; mst1 = mn1;
        lst0 = lst0 * es0 + rs0;
        lst1 = lst1 * es1 + rs1;

        // O = O*escale + P @ V
#pragma unroll
        for (int nt = 0; nt < 16; nt++) {
            o[nt][0] *= es0; o[nt][1] *= es0;
            o[nt][2] *= es1; o[nt][3] *= es1;
        }
#pragma unroll
        for (int kk = 0; kk < 4; kk++) {
            uint32_t a[4];
            a[0] = packh2(s[2 * kk][0],     s[2 * kk][1]);
            a[1] = packh2(s[2 * kk][2],     s[2 * kk][3]);
            a[2] = packh2(s[2 * kk + 1][0], s[2 * kk + 1][1]);
            a[3] = packh2(s[2 * kk + 1][2], s[2 * kk + 1][3]);
#pragma unroll
            for (int ntp = 0; ntp < 8; ntp++) {
                uint32_t vb[4];
                LDSM4T(vb, vbase + kk * 4352 + ntp * 32 + vlane);
                mma16(o[ntp * 2],     a, vb[0], vb[1]);
                mma16(o[ntp * 2 + 1], a, vb[2], vb[3]);
            }
        }
    }
#undef LOADK
#undef LOADV

    // normalize + write ctx (half, for the dense GEMM)
    const float inv0 = 1.f / lst0, inv1 = 1.f / lst1;
#pragma unroll
    for (int nt = 0; nt < 16; nt++) {
        const int ccol = h * HDIM + nt * 8 + 2 * c;
        size_t r0 = ((size_t)((qb * 128 + m0 + g) * 2 + b)) * H_DIM + ccol;
        size_t r1 = ((size_t)((qb * 128 + m0 + g + 8) * 2 + b)) * H_DIM + ccol;
        *(__half2*)&g_ctx[r0] = __floats2half2_rn(o[nt][0] * inv0, o[nt][1] * inv0);
        *(__half2*)&g_ctx[r1] = __floats2half2_rn(o[nt][2] * inv1, o[nt][3] * inv1);
    }
}

// ---------------------------------------------------------------------------
extern "C" void kernel_launch(void* const* d_in, const int* in_sizes, int n_in,
                              void* d_out, int out_size)
{
    const float* hidden = (const float*)d_in[0];
    const float* rope   = (const float*)d_in[2];
    const float* Wqkv   = (const float*)d_in[3];
    const float* bqkv   = (const float*)d_in[4];
    const float* Wd     = (const float*)d_in[5];
    float* out = (float*)d_out;

    __half *mixed, *ctx, *hid, *wq, *wd;
    cudaGetSymbolAddress((void**)&mixed, g_mixed);
    cudaGetSymbolAddress((void**)&ctx,   g_ctx);
    cudaGetSymbolAddress((void**)&hid,   g_hid);
    cudaGetSymbolAddress((void**)&wq,    g_wq);
    cudaGetSymbolAddress((void**)&wd,    g_wd);

    cudaFuncSetAttribute(gemm_mma_kernel,
                         cudaFuncAttributeMaxDynamicSharedMemorySize, GEMM_SMEM);
    cudaFuncSetAttribute(flash_mma_kernel,
                         cudaFuncAttributeMaxDynamicSharedMemorySize, FLASH_SMEM);

    // fused fp16 pre-rounding (RNE) of all GEMM inputs — one launch
    {
        const int n0 = M_ROWS * H_DIM / 4;
        const int n1 = O_QKV * H_DIM / 4;
        const int n2 = H_DIM * H_DIM / 4;
        const int tot = n0 + n1 + n2;
        round_all_kernel<<<(tot + 255) / 256, 256>>>(
            (const float4*)hidden, (__half2*)hid, n0,
            (const float4*)Wqkv,   (__half2*)wq,  n1,
            (const float4*)Wd,     (__half2*)wd,  n2);
    }

    // 1) QKV projection + bias + fused RoPE (half output)
    gemm_mma_kernel<<<dim3(O_QKV / 256, M_ROWS / 128), 512, GEMM_SMEM>>>(
        hid, wq, bqkv, mixed, rope, O_QKV, H_DIM, 1);

    // 2) flash attention (fp16, P in registers, balanced launch order)
    flash_mma_kernel<<<dim3(S_LEN / 128, NHEADS, B_SZ), 256, FLASH_SMEM>>>();

    // 3) dense projection (fp32 output, no rope)
    gemm_mma_kernel<<<dim3(H_DIM / 256, M_ROWS / 128), 512, GEMM_SMEM>>>(
        ctx, wd, nullptr, out, nullptr, H_DIM, H_DIM, 0);
}

// round 14
// speedup vs baseline: 1.1880x; 1.0013x over previous
#include <cuda_runtime.h>
#include <cuda_fp16.h>
#include <math.h>
#include <stdint.h>

#define S_LEN  2048
#define B_SZ   2
#define H_DIM  4096
#define NHEADS 32
#define NGRP   2
#define HDIM   128
#define O_QKV  4608
#define M_ROWS 4096

// ---------------- scratch (__device__ globals; allocation-free rule) --------
__device__ __half g_mixed[M_ROWS * O_QKV];
__device__ __half g_ctx[M_ROWS * H_DIM];
__device__ __half g_hid[M_ROWS * H_DIM];
__device__ __half g_wq[O_QKV * H_DIM];
__device__ __half g_wd[H_DIM * H_DIM];

// ---------------- helpers ----------------------------------------------------
__device__ __forceinline__ uint32_t smem_u32(const void* p) {
    uint32_t a;
    asm("{ .reg .u64 t; cvta.to.shared.u64 t, %1; cvt.u32.u64 %0, t; }" : "=r"(a) : "l"(p));
    return a;
}
__device__ __forceinline__ void cp_async16(uint32_t dst, const void* src) {
    asm volatile("cp.async.cg.shared.global [%0], [%1], 16;" :: "r"(dst), "l"(src));
}
__device__ __forceinline__ void cp_commit() {
    asm volatile("cp.async.commit_group;" ::: "memory");
}
template<int N> __device__ __forceinline__ void cp_wait() {
    asm volatile("cp.async.wait_group %0;" :: "n"(N) : "memory");
}
// D += A*B, m16n8k16 fp16 in / fp32 acc
__device__ __forceinline__ void mma16(float* d, const uint32_t* a, uint32_t b0, uint32_t b1) {
    asm volatile("mma.sync.aligned.m16n8k16.row.col.f32.f16.f16.f32 "
        "{%0,%1,%2,%3}, {%4,%5,%6,%7}, {%8,%9}, {%0,%1,%2,%3};"
        : "+f"(d[0]), "+f"(d[1]), "+f"(d[2]), "+f"(d[3])
        : "r"(a[0]), "r"(a[1]), "r"(a[2]), "r"(a[3]), "r"(b0), "r"(b1));
}
#define LDSM4(r, addr) \
    asm volatile("ldmatrix.sync.aligned.m8n8.x4.shared.b16 {%0,%1,%2,%3}, [%4];" \
        : "=r"((r)[0]), "=r"((r)[1]), "=r"((r)[2]), "=r"((r)[3]) : "r"(addr))
#define LDSM4T(r, addr) \
    asm volatile("ldmatrix.sync.aligned.m8n8.x4.trans.shared.b16 {%0,%1,%2,%3}, [%4];" \
        : "=r"((r)[0]), "=r"((r)[1]), "=r"((r)[2]), "=r"((r)[3]) : "r"(addr))

__device__ __forceinline__ uint32_t h2u(__half2 h) { return *reinterpret_cast<uint32_t*>(&h); }
__device__ __forceinline__ uint32_t packh2(float lo, float hi) {
    __half2 h = __floats2half2_rn(lo, hi);        // low 16 bits = lo
    return *reinterpret_cast<uint32_t*>(&h);
}

// ---------------- fused f32 -> f16 rounding pass (all three tensors) --------
__global__ __launch_bounds__(256) void round_all_kernel(
    const float4* __restrict__ in0, __half2* __restrict__ out0, int n0,
    const float4* __restrict__ in1, __half2* __restrict__ out1, int n1,
    const float4* __restrict__ in2, __half2* __restrict__ out2, int n2)
{
    int i = blockIdx.x * blockDim.x + threadIdx.x;
    const float4* in; __half2* out; int j = i;
    if (j < n0)            { in = in0; out = out0; }
    else if ((j -= n0) < n1) { in = in1; out = out1; }
    else if ((j -= n1) < n2) { in = in2; out = out2; }
    else return;
    float4 v = in[j];
    out[2 * j]     = __floats2half2_rn(v.x, v.y);
    out[2 * j + 1] = __floats2half2_rn(v.z, v.w);
}

// ---------------- fp16 mma GEMM: C[M,N] = A[M,K] @ W[N,K]^T (+bias) ---------
// 512 thr (16 warps, warp grid 2Mx8N, warp tile 64x32), CTA 128x256.
// K-chunk 64 halves, 4-stage cp.async (3 chunks in flight), ldmatrix frags.
// Optional fused RoPE in the epilogue (QKV path).
#define A_STG_B (128 * 144)            // 18432
#define B_STG_B (256 * 144)            // 36864
#define STG_B   (A_STG_B + B_STG_B)    // 55296
#define GEMM_SMEM (4 * STG_B)          // 221184

__global__ __launch_bounds__(512, 1) void gemm_mma_kernel(
    const __half* __restrict__ A, const __half* __restrict__ W,
    const float* __restrict__ bias, void* __restrict__ Cv,
    const float* __restrict__ rope,
    int N, int K, int out_half)
{
    extern __shared__ char smc[];
    const uint32_t sb = smem_u32(smc);

    const int tid = threadIdx.x;
    const int wid = tid >> 5, lid = tid & 31;
    const int g = lid >> 2, c = lid & 3;
    const int m4 = lid >> 3, r8 = lid & 7;
    const int m0 = (wid & 1) * 64, n0 = (wid >> 1) * 32;
    const int row0 = blockIdx.y * 128;
    const int col0 = blockIdx.x * 256;

    const uint32_t laneA = ((m4 & 1) * 8 + r8) * 144 + (m4 >> 1) * 16;
    const uint32_t laneB = ((m4 >> 1) * 8 + r8) * 144 + (m4 & 1) * 16;

    float acc[4][4][4];
#pragma unroll
    for (int i = 0; i < 4; i++)
#pragma unroll
        for (int j = 0; j < 4; j++)
#pragma unroll
            for (int k = 0; k < 4; k++) acc[i][j][k] = 0.f;

    const int nchunk = K / 64;
    const int arow = tid >> 2;
    const int aseg = (tid & 3) * 2;
    const int brow = tid >> 1;
    const int bseg = (tid & 1) * 4;

#define LOADCH(ch, st) do {                                                    \
        const __half* _a = A + (size_t)(row0 + arow) * K + (ch) * 64;          \
        const __half* _b = W + (size_t)(col0 + brow) * K + (ch) * 64;          \
        uint32_t _da = sb + (st) * STG_B + arow * 144;                         \
        uint32_t _db = sb + (st) * STG_B + A_STG_B + brow * 144;               \
        cp_async16(_da + (aseg + 0) * 16, _a + (aseg + 0) * 8);                \
        cp_async16(_da + (aseg + 1) * 16, _a + (aseg + 1) * 8);                \
        cp_async16(_db + (bseg + 0) * 16, _b + (bseg + 0) * 8);                \
        cp_async16(_db + (bseg + 1) * 16, _b + (bseg + 1) * 8);                \
        cp_async16(_db + (bseg + 2) * 16, _b + (bseg + 2) * 8);                \
        cp_async16(_db + (bseg + 3) * 16, _b + (bseg + 3) * 8);                \
        cp_commit();                                                           \
    } while (0)

    LOADCH(0, 0);
    LOADCH(1, 1);
    LOADCH(2, 2);

    for (int i = 0; i < nchunk; i++) {
        if (i + 1 < nchunk) cp_wait<2>(); else cp_wait<0>();
        __syncthreads();
        if (i + 3 < nchunk) LOADCH(i + 3, (i + 3) & 3);

        const uint32_t stA = sb + (i & 3) * STG_B;
        const uint32_t stB = stA + A_STG_B;
#pragma unroll
        for (int kk = 0; kk < 4; kk++) {
            uint32_t af[4][4], bf[2][4];
#pragma unroll
            for (int mt = 0; mt < 4; mt++)
                LDSM4(af[mt], stA + (m0 + mt * 16) * 144 + kk * 32 + laneA);
#pragma unroll
            for (int np = 0; np < 2; np++)
                LDSM4(bf[np], stB + (n0 + np * 16) * 144 + kk * 32 + laneB);
#pragma unroll
            for (int mt = 0; mt < 4; mt++)
#pragma unroll
                for (int np = 0; np < 2; np++) {
                    mma16(acc[mt][np * 2],     af[mt], bf[np][0], bf[np][1]);
                    mma16(acc[mt][np * 2 + 1], af[mt], bf[np][2], bf[np][3]);
                }
        }
    }
#undef LOADCH

    // epilogue (+bias, optional fused RoPE, fp16 or fp32 output)
#pragma unroll
    for (int mt = 0; mt < 4; mt++) {
#pragma unroll
        for (int nt = 0; nt < 4; nt++) {
            const int rr = row0 + m0 + mt * 16 + g;
            const int cc = col0 + n0 + nt * 8 + 2 * c;
            float b0 = bias ? bias[cc] : 0.f;
            float b1 = bias ? bias[cc + 1] : 0.f;
            float v00 = acc[mt][nt][0] + b0, v01 = acc[mt][nt][1] + b1;
            float v10 = acc[mt][nt][2] + b0, v11 = acc[mt][nt][3] + b1;
            if (rope) {
                const int d = cc & 127;
                if (cc < 4352 && d < 64) {
                    const int s0 = rr >> 1, s1 = (rr + 8) >> 1;
                    float c0 = rope[s0 * 64 + d], sn0 = rope[s0 * 64 + d + 1];
                    float c1 = rope[s1 * 64 + d], sn1 = rope[s1 * 64 + d + 1];
                    float t00 = v00 * c0 - v01 * sn0;
                    float t01 = v01 * c0 + v00 * sn0;
                    float t10 = v10 * c1 - v11 * sn1;
                    float t11 = v11 * c1 + v10 * sn1;
                    v00 = t00; v01 = t01; v10 = t10; v11 = t11;
                }
            }
            if (out_half) {
                __half* C = (__half*)Cv;
                *(__half2*)&C[(size_t)rr * N + cc]       = __floats2half2_rn(v00, v01);
                *(__half2*)&C[(size_t)(rr + 8) * N + cc] = __floats2half2_rn(v10, v11);
            } else {
                float* C = (float*)Cv;
                *(float2*)&C[(size_t)rr * N + cc]       = make_float2(v00, v01);
                *(float2*)&C[(size_t)(rr + 8) * N + cc] = make_float2(v10, v11);
            }
        }
    }
}

// ---------------- flash attention fp16, BQ=128, P-in-registers --------------
// 256 thr / 8 warps; warp w owns Q rows [w*16, w*16+16).
// K/V double-buffered via cp.async; K B-frags via ldmatrix (non-trans),
// V B-frags via ldmatrix.trans.  qb launched in DESCENDING work order.
// smem: K0,K1,V0,V1 each 64 rows x 272 B (136-half stride) = 17408 B.
#define KB0 0
#define KB1 17408
#define VB0 34816
#define VB1 52224
#define FLASH_SMEM 69632

__global__ __launch_bounds__(256, 1) void flash_mma_kernel()
{
    extern __shared__ char smf[];
    const uint32_t sbase = smem_u32(smf);

    const int qb = gridDim.x - 1 - blockIdx.x;   // long CTAs first
    const int h = blockIdx.y, b = blockIdx.z;
    const int grp = h >> 4;
    const int tid = threadIdx.x, wid = tid >> 5, lid = tid & 31;
    const int g = lid >> 2, c = lid & 3;
    const int m4 = lid >> 3, r8 = lid & 7;
    const int m0 = wid * 16;
    const float scale = 0.08838834764831843f;

    // ldmatrix per-lane byte offsets into K/V buffers (272 B row stride)
    const uint32_t vlane = ((m4 & 1) * 8 + r8) * 272 + (m4 >> 1) * 16;
    const uint32_t klane = ((m4 >> 1) * 8 + r8) * 272 + (m4 & 1) * 16;

#define LOADK(kb, p) do {                                                       \
        _Pragma("unroll")                                                       \
        for (int _s = 0; _s < 4; _s++) {                                        \
            int _ln = tid + _s * 256;                                           \
            int _r = _ln >> 4, _c = _ln & 15;                                   \
            cp_async16(sbase + ((p) ? KB1 : KB0) + _r * 272 + _c * 16,          \
                &g_mixed[((size_t)(((kb) * 64 + _r) * 2 + b)) * O_QKV           \
                         + 4096 + grp * HDIM + _c * 8]);                        \
        } } while (0)
#define LOADV(kb, p) do {                                                       \
        _Pragma("unroll")                                                       \
        for (int _s = 0; _s < 4; _s++) {                                        \
            int _ln = tid + _s * 256;                                           \
            int _r = _ln >> 4, _c = _ln & 15;                                   \
            cp_async16(sbase + ((p) ? VB1 : VB0) + _r * 272 + _c * 16,          \
                &g_mixed[((size_t)(((kb) * 64 + _r) * 2 + b)) * O_QKV           \
                         + 4352 + grp * HDIM + _c * 8]);                        \
        } } while (0)

    // ---- stage Q into KB1/VB1 AND issue kb=0 K/V into KB0/VB0: one group ----
#pragma unroll
    for (int s = 0; s < 8; s++) {
        int ln = tid + s * 256;            // 0..2047
        int r = ln >> 4, cseg = ln & 15;
        uint32_t dst = (r < 64) ? (sbase + KB1 + r * 272 + cseg * 16)
                                : (sbase + VB1 + (r - 64) * 272 + cseg * 16);
        cp_async16(dst, &g_mixed[((size_t)((qb * 128 + r) * 2 + b)) * O_QKV
                                 + h * HDIM + cseg * 8]);
    }
    LOADK(0, 0); LOADV(0, 0);
    cp_commit();
    cp_wait<0>();
    __syncthreads();

    uint32_t qf[8][4];
    {
        const __half2* q2 = (const __half2*)(smf + ((wid < 4) ? KB1 : VB1));
        const int rl = (m0 & 63) + g;
#pragma unroll
        for (int kk = 0; kk < 8; kk++) {
            qf[kk][0] = h2u(q2[rl * 68 + kk * 8 + c]);
            qf[kk][1] = h2u(q2[(rl + 8) * 68 + kk * 8 + c]);
            qf[kk][2] = h2u(q2[rl * 68 + kk * 8 + c + 4]);
            qf[kk][3] = h2u(q2[(rl + 8) * 68 + kk * 8 + c + 4]);
        }
    }
    __syncthreads();   // all warps done reading KB1/VB1 before kb=1 load

    float o[16][4];
#pragma unroll
    for (int nt = 0; nt < 16; nt++)
#pragma unroll
        for (int j = 0; j < 4; j++) o[nt][j] = 0.f;
    float mst0 = -INFINITY, mst1 = -INFINITY, lst0 = 0.f, lst1 = 0.f;

    const int nkb = 2 * qb + 2;

    for (int kb = 0; kb < nkb; kb++) {
        const int p = kb & 1;
        cp_wait<0>();
        __syncthreads();
        if (kb + 1 < nkb) { LOADK(kb + 1, p ^ 1); LOADV(kb + 1, p ^ 1); cp_commit(); }

        const uint32_t kbase = sbase + (p ? KB1 : KB0);
        const uint32_t vbase = sbase + (p ? VB1 : VB0);

        // S = Q @ K^T  (K B-fragments via ldmatrix.x4: 4 per kk)
        float s[8][4];
#pragma unroll
        for (int nt = 0; nt < 8; nt++)
#pragma unroll
            for (int j = 0; j < 4; j++) s[nt][j] = 0.f;
#pragma unroll
        for (int kk = 0; kk < 8; kk++) {
#pragma unroll
            for (int j = 0; j < 4; j++) {
                uint32_t kf[4];
                LDSM4(kf, kbase + j * (16 * 272) + kk * 32 + klane);
                mma16(s[2 * j],     qf[kk], kf[0], kf[1]);
                mma16(s[2 * j + 1], qf[kk], kf[2], kf[3]);
            }
        }

        if (kb >= 2 * qb) {        // causal mask (diagonal region)
            const int r0 = qb * 128 + m0 + g, r1 = r0 + 8;
            const int cb = kb * 64;
#pragma unroll
            for (int nt = 0; nt < 8; nt++) {
                const int n = cb + nt * 8 + 2 * c;
                if (n > r0)     s[nt][0] = -1e30f;
                if (n + 1 > r0) s[nt][1] = -1e30f;
                if (n > r1)     s[nt][2] = -1e30f;
                if (n + 1 > r1) s[nt][3] = -1e30f;
            }
        }

        // online softmax, scale folded
        float rm0 = -INFINITY, rm1 = -INFINITY;
#pragma unroll
        for (int nt = 0; nt < 8; nt++) {
            rm0 = fmaxf(rm0, fmaxf(s[nt][0], s[nt][1]));
            rm1 = fmaxf(rm1, fmaxf(s[nt][2], s[nt][3]));
        }
        rm0 = fmaxf(rm0, __shfl_xor_sync(0xffffffffu, rm0, 1));
        rm0 = fmaxf(rm0, __shfl_xor_sync(0xffffffffu, rm0, 2));
        rm1 = fmaxf(rm1, __shfl_xor_sync(0xffffffffu, rm1, 1));
        rm1 = fmaxf(rm1, __shfl_xor_sync(0xffffffffu, rm1, 2));
        const float mn0 = fmaxf(mst0, rm0);
        const float mn1 = fmaxf(mst1, rm1);
        const float es0 = __expf((mst0 - mn0) * scale);
        const float es1 = __expf((mst1 - mn1) * scale);
        float rs0 = 0.f, rs1 = 0.f;
#pragma unroll
        for (int nt = 0; nt < 8; nt++) {
            s[nt][0] = __expf((s[nt][0] - mn0) * scale);
            s[nt][1] = __expf((s[nt][1] - mn0) * scale);
            s[nt][2] = __expf((s[nt][2] - mn1) * scale);
            s[nt][3] = __expf((s[nt][3] - mn1) * scale);
            rs0 += s[nt][0] + s[nt][1];
            rs1 += s[nt][2] + s[nt][3];
        }
        rs0 += __shfl_xor_sync(0xffffffffu, rs0, 1);
        rs0 += __shfl_xor_sync(0xffffffffu, rs0, 2);
        rs1 += __shfl_xor_sync(0xffffffffu, rs1, 1);
        rs1 += __shfl_xor_sync(0xffffffffu, rs1, 2);
        mst0 = mn0; mst1 = mn1;
        lst0 = lst0 * es0 + rs0;
        lst1 = lst1 * es1 + rs1;

        // O = O*escale + P @ V
#pragma unroll
        for (int nt = 0; nt < 16; nt++) {
            o[nt][0] *= es0; o[nt][1] *= es0;
            o[nt][2] *= es1; o[nt][3] *= es1;
        }
#pragma unroll
        for (int kk = 0; kk < 4; kk++) {
            uint32_t a[4];
            a[0] = packh2(s[2 * kk][0],     s[2 * kk][1]);
            a[1] = packh2(s[2 * kk][2],     s[2 * kk][3]);
            a[2] = packh2(s[2 * kk + 1][0], s[2 * kk + 1][1]);
            a[3] = packh2(s[2 * kk + 1][2], s[2 * kk + 1][3]);
#pragma unroll
            for (int ntp = 0; ntp < 8; ntp++) {
                uint32_t vb[4];
                LDSM4T(vb, vbase + kk * 4352 + ntp * 32 + vlane);
                mma16(o[ntp * 2],     a, vb[0], vb[1]);
                mma16(o[ntp * 2 + 1], a, vb[2], vb[3]);
            }
        }
    }
#undef LOADK
#undef LOADV

    // normalize + write ctx (half, for the dense GEMM)
    const float inv0 = 1.f / lst0, inv1 = 1.f / lst1;
#pragma unroll
    for (int nt = 0; nt < 16; nt++) {
        const int ccol = h * HDIM + nt * 8 + 2 * c;
        size_t r0 = ((size_t)((qb * 128 + m0 + g) * 2 + b)) * H_DIM + ccol;
        size_t r1 = ((size_t)((qb * 128 + m0 + g + 8) * 2 + b)) * H_DIM + ccol;
        *(__half2*)&g_ctx[r0] = __floats2half2_rn(o[nt][0] * inv0, o[nt][1] * inv0);
        *(__half2*)&g_ctx[r1] = __floats2half2_rn(o[nt][2] * inv1, o[nt][3] * inv1);
    }
}

// ---------------------------------------------------------------------------
extern "C" void kernel_launch(void* const* d_in, const int* in_sizes, int n_in,
                              void* d_out, int out_size)
{
    const float* hidden = (const float*)d_in[0];
    const float* rope   = (const float*)d_in[2];
    const float* Wqkv   = (const float*)d_in[3];
    const float* bqkv   = (const float*)d_in[4];
    const float* Wd     = (const float*)d_in[5];
    float* out = (float*)d_out;

    __half *mixed, *ctx, *hid, *wq, *wd;
    cudaGetSymbolAddress((void**)&mixed, g_mixed);
    cudaGetSymbolAddress((void**)&ctx,   g_ctx);
    cudaGetSymbolAddress((void**)&hid,   g_hid);
    cudaGetSymbolAddress((void**)&wq,    g_wq);
    cudaGetSymbolAddress((void**)&wd,    g_wd);

    cudaFuncSetAttribute(gemm_mma_kernel,
                         cudaFuncAttributeMaxDynamicSharedMemorySize, GEMM_SMEM);
    cudaFuncSetAttribute(flash_mma_kernel,
                         cudaFuncAttributeMaxDynamicSharedMemorySize, FLASH_SMEM);

    // fused fp16 pre-rounding (RNE) of all GEMM inputs — one launch
    {
        const int n0 = M_ROWS * H_DIM / 4;
        const int n1 = O_QKV * H_DIM / 4;
        const int n2 = H_DIM * H_DIM / 4;
        const int tot = n0 + n1 + n2;
        round_all_kernel<<<(tot + 255) / 256, 256>>>(
            (const float4*)hidden, (__half2*)hid, n0,
            (const float4*)Wqkv,   (__half2*)wq,  n1,
            (const float4*)Wd,     (__half2*)wd,  n2);
    }

    // 1) QKV projection + bias + fused RoPE (half output)
    gemm_mma_kernel<<<dim3(O_QKV / 256, M_ROWS / 128), 512, GEMM_SMEM>>>(
        hid, wq, bqkv, mixed, rope, O_QKV, H_DIM, 1);

    // 2) flash attention (fp16, ldmatrix K+V, balanced launch order)
    flash_mma_kernel<<<dim3(S_LEN / 128, NHEADS, B_SZ), 256, FLASH_SMEM>>>();

    // 3) dense projection (fp32 output, no rope)
    gemm_mma_kernel<<<dim3(H_DIM / 256, M_ROWS / 128), 512, GEMM_SMEM>>>(
        ctx, wd, nullptr, out, nullptr, H_DIM, H_DIM, 0);
}

// round 15
// speedup vs baseline: 1.1966x; 1.0072x over previous
#include <cuda_runtime.h>
#include <cuda_fp16.h>
#include <math.h>
#include <stdint.h>

#define S_LEN  2048
#define B_SZ   2
#define H_DIM  4096
#define NHEADS 32
#define NGRP   2
#define HDIM   128
#define O_QKV  4608
#define M_ROWS 4096

// ---------------- scratch (__device__ globals; allocation-free rule) --------
__device__ __half g_mixed[M_ROWS * O_QKV];
__device__ __half g_ctx[M_ROWS * H_DIM];
__device__ __half g_hid[M_ROWS * H_DIM];
__device__ __half g_wq[O_QKV * H_DIM];
__device__ __half g_wd[H_DIM * H_DIM];

// ---------------- helpers ----------------------------------------------------
__device__ __forceinline__ uint32_t smem_u32(const void* p) {
    uint32_t a;
    asm("{ .reg .u64 t; cvta.to.shared.u64 t, %1; cvt.u32.u64 %0, t; }" : "=r"(a) : "l"(p));
    return a;
}
__device__ __forceinline__ void cp_async16(uint32_t dst, const void* src) {
    asm volatile("cp.async.cg.shared.global [%0], [%1], 16;" :: "r"(dst), "l"(src));
}
__device__ __forceinline__ void cp_commit() {
    asm volatile("cp.async.commit_group;" ::: "memory");
}
template<int N> __device__ __forceinline__ void cp_wait() {
    asm volatile("cp.async.wait_group %0;" :: "n"(N) : "memory");
}
// D += A*B, m16n8k16 fp16 in / fp32 acc
__device__ __forceinline__ void mma16(float* d, const uint32_t* a, uint32_t b0, uint32_t b1) {
    asm volatile("mma.sync.aligned.m16n8k16.row.col.f32.f16.f16.f32 "
        "{%0,%1,%2,%3}, {%4,%5,%6,%7}, {%8,%9}, {%0,%1,%2,%3};"
        : "+f"(d[0]), "+f"(d[1]), "+f"(d[2]), "+f"(d[3])
        : "r"(a[0]), "r"(a[1]), "r"(a[2]), "r"(a[3]), "r"(b0), "r"(b1));
}
#define LDSM4(r, addr) \
    asm volatile("ldmatrix.sync.aligned.m8n8.x4.shared.b16 {%0,%1,%2,%3}, [%4];" \
        : "=r"((r)[0]), "=r"((r)[1]), "=r"((r)[2]), "=r"((r)[3]) : "r"(addr))
#define LDSM4T(r, addr) \
    asm volatile("ldmatrix.sync.aligned.m8n8.x4.trans.shared.b16 {%0,%1,%2,%3}, [%4];" \
        : "=r"((r)[0]), "=r"((r)[1]), "=r"((r)[2]), "=r"((r)[3]) : "r"(addr))

__device__ __forceinline__ uint32_t h2u(__half2 h) { return *reinterpret_cast<uint32_t*>(&h); }
__device__ __forceinline__ uint32_t packh2(float lo, float hi) {
    __half2 h = __floats2half2_rn(lo, hi);        // low 16 bits = lo
    return *reinterpret_cast<uint32_t*>(&h);
}

// ---------------- fused f32 -> f16 rounding pass (all three tensors) --------
__global__ __launch_bounds__(256) void round_all_kernel(
    const float4* __restrict__ in0, __half2* __restrict__ out0, int n0,
    const float4* __restrict__ in1, __half2* __restrict__ out1, int n1,
    const float4* __restrict__ in2, __half2* __restrict__ out2, int n2)
{
    int i = blockIdx.x * blockDim.x + threadIdx.x;
    const float4* in; __half2* out; int j = i;
    if (j < n0)            { in = in0; out = out0; }
    else if ((j -= n0) < n1) { in = in1; out = out1; }
    else if ((j -= n1) < n2) { in = in2; out = out2; }
    else return;
    float4 v = in[j];
    out[2 * j]     = __floats2half2_rn(v.x, v.y);
    out[2 * j + 1] = __floats2half2_rn(v.z, v.w);
}

// ---------------- fp16 mma GEMM: C[M,N] = A[M,K] @ W[N,K]^T (+bias) ---------
// 512 thr (16 warps, warp grid 2Mx8N, warp tile 64x32), CTA 128x256.
// K-chunk 64 halves; TWO chunks per barrier (32 sync points per tile).
// 4-stage smem ring; ldmatrix fragments; optional fused RoPE epilogue.
#define A_STG_B (128 * 144)            // 18432
#define B_STG_B (256 * 144)            // 36864
#define STG_B   (A_STG_B + B_STG_B)    // 55296
#define GEMM_SMEM (4 * STG_B)          // 221184

__global__ __launch_bounds__(512, 1) void gemm_mma_kernel(
    const __half* __restrict__ A, const __half* __restrict__ W,
    const float* __restrict__ bias, void* __restrict__ Cv,
    const float* __restrict__ rope,
    int N, int K, int out_half)
{
    extern __shared__ char smc[];
    const uint32_t sb = smem_u32(smc);

    const int tid = threadIdx.x;
    const int wid = tid >> 5, lid = tid & 31;
    const int g = lid >> 2, c = lid & 3;
    const int m4 = lid >> 3, r8 = lid & 7;
    const int m0 = (wid & 1) * 64, n0 = (wid >> 1) * 32;
    const int row0 = blockIdx.y * 128;
    const int col0 = blockIdx.x * 256;

    const uint32_t laneA = ((m4 & 1) * 8 + r8) * 144 + (m4 >> 1) * 16;
    const uint32_t laneB = ((m4 >> 1) * 8 + r8) * 144 + (m4 & 1) * 16;

    float acc[4][4][4];
#pragma unroll
    for (int i = 0; i < 4; i++)
#pragma unroll
        for (int j = 0; j < 4; j++)
#pragma unroll
            for (int k = 0; k < 4; k++) acc[i][j][k] = 0.f;

    const int nchunk = K / 64;                 // even (K = 4096)
    const int arow = tid >> 2;
    const int aseg = (tid & 3) * 2;
    const int brow = tid >> 1;
    const int bseg = (tid & 1) * 4;

#define LOADCH(ch, st) do {                                                    \
        const __half* _a = A + (size_t)(row0 + arow) * K + (ch) * 64;          \
        const __half* _b = W + (size_t)(col0 + brow) * K + (ch) * 64;          \
        uint32_t _da = sb + (st) * STG_B + arow * 144;                         \
        uint32_t _db = sb + (st) * STG_B + A_STG_B + brow * 144;               \
        cp_async16(_da + (aseg + 0) * 16, _a + (aseg + 0) * 8);                \
        cp_async16(_da + (aseg + 1) * 16, _a + (aseg + 1) * 8);                \
        cp_async16(_db + (bseg + 0) * 16, _b + (bseg + 0) * 8);                \
        cp_async16(_db + (bseg + 1) * 16, _b + (bseg + 1) * 8);                \
        cp_async16(_db + (bseg + 2) * 16, _b + (bseg + 2) * 8);                \
        cp_async16(_db + (bseg + 3) * 16, _b + (bseg + 3) * 8);                \
    } while (0)

    LOADCH(0, 0);
    LOADCH(1, 1);
    cp_commit();

    for (int i = 0; i < nchunk; i += 2) {
        cp_wait<0>();          // chunks i, i+1 resident (committed last iter)
        __syncthreads();
        if (i + 2 < nchunk) {  // prefetch next pair into the other two stages
            LOADCH(i + 2, (i + 2) & 3);
            LOADCH(i + 3, (i + 3) & 3);
            cp_commit();
        }
#pragma unroll
        for (int h = 0; h < 2; h++) {
            const uint32_t stA = sb + ((i + h) & 3) * STG_B;
            const uint32_t stB = stA + A_STG_B;
#pragma unroll
            for (int kk = 0; kk < 4; kk++) {
                uint32_t af[4][4], bf[2][4];
#pragma unroll
                for (int mt = 0; mt < 4; mt++)
                    LDSM4(af[mt], stA + (m0 + mt * 16) * 144 + kk * 32 + laneA);
#pragma unroll
                for (int np = 0; np < 2; np++)
                    LDSM4(bf[np], stB + (n0 + np * 16) * 144 + kk * 32 + laneB);
#pragma unroll
                for (int mt = 0; mt < 4; mt++)
#pragma unroll
                    for (int np = 0; np < 2; np++) {
                        mma16(acc[mt][np * 2],     af[mt], bf[np][0], bf[np][1]);
                        mma16(acc[mt][np * 2 + 1], af[mt], bf[np][2], bf[np][3]);
                    }
            }
        }
    }
#undef LOADCH

    // epilogue (+bias, optional fused RoPE, fp16 or fp32 output)
#pragma unroll
    for (int mt = 0; mt < 4; mt++) {
#pragma unroll
        for (int nt = 0; nt < 4; nt++) {
            const int rr = row0 + m0 + mt * 16 + g;
            const int cc = col0 + n0 + nt * 8 + 2 * c;
            float b0 = bias ? bias[cc] : 0.f;
            float b1 = bias ? bias[cc + 1] : 0.f;
            float v00 = acc[mt][nt][0] + b0, v01 = acc[mt][nt][1] + b1;
            float v10 = acc[mt][nt][2] + b0, v11 = acc[mt][nt][3] + b1;
            if (rope) {
                const int d = cc & 127;
                if (cc < 4352 && d < 64) {
                    const int s0 = rr >> 1, s1 = (rr + 8) >> 1;
                    float c0 = rope[s0 * 64 + d], sn0 = rope[s0 * 64 + d + 1];
                    float c1 = rope[s1 * 64 + d], sn1 = rope[s1 * 64 + d + 1];
                    float t00 = v00 * c0 - v01 * sn0;
                    float t01 = v01 * c0 + v00 * sn0;
                    float t10 = v10 * c1 - v11 * sn1;
                    float t11 = v11 * c1 + v10 * sn1;
                    v00 = t00; v01 = t01; v10 = t10; v11 = t11;
                }
            }
            if (out_half) {
                __half* C = (__half*)Cv;
                *(__half2*)&C[(size_t)rr * N + cc]       = __floats2half2_rn(v00, v01);
                *(__half2*)&C[(size_t)(rr + 8) * N + cc] = __floats2half2_rn(v10, v11);
            } else {
                float* C = (float*)Cv;
                *(float2*)&C[(size_t)rr * N + cc]       = make_float2(v00, v01);
                *(float2*)&C[(size_t)(rr + 8) * N + cc] = make_float2(v10, v11);
            }
        }
    }
}

// ---------------- flash attention fp16, BQ=128, P-in-registers --------------
// 256 thr / 8 warps; warp w owns Q rows [w*16, w*16+16).
// K/V double-buffered via cp.async; K B-frags via ldmatrix (non-trans),
// V B-frags via ldmatrix.trans.  qb launched in DESCENDING work order.
// smem: K0,K1,V0,V1 each 64 rows x 272 B (136-half stride) = 17408 B.
#define KB0 0
#define KB1 17408
#define VB0 34816
#define VB1 52224
#define FLASH_SMEM 69632

__global__ __launch_bounds__(256, 1) void flash_mma_kernel()
{
    extern __shared__ char smf[];
    const uint32_t sbase = smem_u32(smf);

    const int qb = gridDim.x - 1 - blockIdx.x;   // long CTAs first
    const int h = blockIdx.y, b = blockIdx.z;
    const int grp = h >> 4;
    const int tid = threadIdx.x, wid = tid >> 5, lid = tid & 31;
    const int g = lid >> 2, c = lid & 3;
    const int m4 = lid >> 3, r8 = lid & 7;
    const int m0 = wid * 16;
    const float scale = 0.08838834764831843f;

    const uint32_t vlane = ((m4 & 1) * 8 + r8) * 272 + (m4 >> 1) * 16;
    const uint32_t klane = ((m4 >> 1) * 8 + r8) * 272 + (m4 & 1) * 16;

#define LOADK(kb, p) do {                                                       \
        _Pragma("unroll")                                                       \
        for (int _s = 0; _s < 4; _s++) {                                        \
            int _ln = tid + _s * 256;                                           \
            int _r = _ln >> 4, _c = _ln & 15;                                   \
            cp_async16(sbase + ((p) ? KB1 : KB0) + _r * 272 + _c * 16,          \
                &g_mixed[((size_t)(((kb) * 64 + _r) * 2 + b)) * O_QKV           \
                         + 4096 + grp * HDIM + _c * 8]);                        \
        } } while (0)
#define LOADV(kb, p) do {                                                       \
        _Pragma("unroll")                                                       \
        for (int _s = 0; _s < 4; _s++) {                                        \
            int _ln = tid + _s * 256;                                           \
            int _r = _ln >> 4, _c = _ln & 15;                                   \
            cp_async16(sbase + ((p) ? VB1 : VB0) + _r * 272 + _c * 16,          \
                &g_mixed[((size_t)(((kb) * 64 + _r) * 2 + b)) * O_QKV           \
                         + 4352 + grp * HDIM + _c * 8]);                        \
        } } while (0)

    // ---- stage Q into KB1/VB1 AND issue kb=0 K/V into KB0/VB0: one group ----
#pragma unroll
    for (int s = 0; s < 8; s++) {
        int ln = tid + s * 256;            // 0..2047
        int r = ln >> 4, cseg = ln & 15;
        uint32_t dst = (r < 64) ? (sbase + KB1 + r * 272 + cseg * 16)
                                : (sbase + VB1 + (r - 64) * 272 + cseg * 16);
        cp_async16(dst, &g_mixed[((size_t)((qb * 128 + r) * 2 + b)) * O_QKV
                                 + h * HDIM + cseg * 8]);
    }
    LOADK(0, 0); LOADV(0, 0);
    cp_commit();
    cp_wait<0>();
    __syncthreads();

    uint32_t qf[8][4];
    {
        const __half2* q2 = (const __half2*)(smf + ((wid < 4) ? KB1 : VB1));
        const int rl = (m0 & 63) + g;
#pragma unroll
        for (int kk = 0; kk < 8; kk++) {
            qf[kk][0] = h2u(q2[rl * 68 + kk * 8 + c]);
            qf[kk][1] = h2u(q2[(rl + 8) * 68 + kk * 8 + c]);
            qf[kk][2] = h2u(q2[rl * 68 + kk * 8 + c + 4]);
            qf[kk][3] = h2u(q2[(rl + 8) * 68 + kk * 8 + c + 4]);
        }
    }
    __syncthreads();   // all warps done reading KB1/VB1 before kb=1 load

    float o[16][4];
#pragma unroll
    for (int nt = 0; nt < 16; nt++)
#pragma unroll
        for (int j = 0; j < 4; j++) o[nt][j] = 0.f;
    float mst0 = -INFINITY, mst1 = -INFINITY, lst0 = 0.f, lst1 = 0.f;

    const int nkb = 2 * qb + 2;

    for (int kb = 0; kb < nkb; kb++) {
        const int p = kb & 1;
        cp_wait<0>();
        __syncthreads();
        if (kb + 1 < nkb) { LOADK(kb + 1, p ^ 1); LOADV(kb + 1, p ^ 1); cp_commit(); }

        const uint32_t kbase = sbase + (p ? KB1 : KB0);
        const uint32_t vbase = sbase + (p ? VB1 : VB0);

        // S = Q @ K^T  (K B-fragments via ldmatrix.x4: 4 per kk)
        float s[8][4];
#pragma unroll
        for (int nt = 0; nt < 8; nt++)
#pragma unroll
            for (int j = 0; j < 4; j++) s[nt][j] = 0.f;
#pragma unroll
        for (int kk = 0; kk < 8; kk++) {
#pragma unroll
            for (int j = 0; j < 4; j++) {
                uint32_t kf[4];
                LDSM4(kf, kbase + j * (16 * 272) + kk * 32 + klane);
                mma16(s[2 * j],     qf[kk], kf[0], kf[1]);
                mma16(s[2 * j + 1], qf[kk], kf[2], kf[3]);
            }
        }

        if (kb >= 2 * qb) {        // causal mask (diagonal region)
            const int r0 = qb * 128 + m0 + g, r1 = r0 + 8;
            const int cb = kb * 64;
#pragma unroll
            for (int nt = 0; nt < 8; nt++) {
                const int n = cb + nt * 8 + 2 * c;
                if (n > r0)     s[nt][0] = -1e30f;
                if (n + 1 > r0) s[nt][1] = -1e30f;
                if (n > r1)     s[nt][2] = -1e30f;
                if (n + 1 > r1) s[nt][3] = -1e30f;
            }
        }

        // online softmax, scale folded
        float rm0 = -INFINITY, rm1 = -INFINITY;
#pragma unroll
        for (int nt = 0; nt < 8; nt++) {
            rm0 = fmaxf(rm0, fmaxf(s[nt][0], s[nt][1]));
            rm1 = fmaxf(rm1, fmaxf(s[nt][2], s[nt][3]));
        }
        rm0 = fmaxf(rm0, __shfl_xor_sync(0xffffffffu, rm0, 1));
        rm0 = fmaxf(rm0, __shfl_xor_sync(0xffffffffu, rm0, 2));
        rm1 = fmaxf(rm1, __shfl_xor_sync(0xffffffffu, rm1, 1));
        rm1 = fmaxf(rm1, __shfl_xor_sync(0xffffffffu, rm1, 2));
        const float mn0 = fmaxf(mst0, rm0);
        const float mn1 = fmaxf(mst1, rm1);
        const float es0 = __expf((mst0 - mn0) * scale);
        const float es1 = __expf((mst1 - mn1) * scale);
        float rs0 = 0.f, rs1 = 0.f;
#pragma unroll
        for (int nt = 0; nt < 8; nt++) {
            s[nt][0] = __expf((s[nt][0] - mn0) * scale);
            s[nt][1] = __expf((s[nt][1] - mn0) * scale);
            s[nt][2] = __expf((s[nt][2] - mn1) * scale);
            s[nt][3] = __expf((s[nt][3] - mn1) * scale);
            rs0 += s[nt][0] + s[nt][1];
            rs1 += s[nt][2] + s[nt][3];
        }
        rs0 += __shfl_xor_sync(0xffffffffu, rs0, 1);
        rs0 += __shfl_xor_sync(0xffffffffu, rs0, 2);
        rs1 += __shfl_xor_sync(0xffffffffu, rs1, 1);
        rs1 += __shfl_xor_sync(0xffffffffu, rs1, 2);
        mst0 = mn0; mst1 = mn1;
        lst0 = lst0 * es0 + rs0;
        lst1 = lst1 * es1 + rs1;

        // O = O*escale + P @ V
#pragma unroll
        for (int nt = 0; nt < 16; nt++) {
            o[nt][0] *= es0; o[nt][1] *= es0;
            o[nt][2] *= es1; o[nt][3] *= es1;
        }
#pragma unroll
        for (int kk = 0; kk < 4; kk++) {
            uint32_t a[4];
            a[0] = packh2(s[2 * kk][0],     s[2 * kk][1]);
            a[1] = packh2(s[2 * kk][2],     s[2 * kk][3]);
            a[2] = packh2(s[2 * kk + 1][0], s[2 * kk + 1][1]);
            a[3] = packh2(s[2 * kk + 1][2], s[2 * kk + 1][3]);
#pragma unroll
            for (int ntp = 0; ntp < 8; ntp++) {
                uint32_t vb[4];
                LDSM4T(vb, vbase + kk * 4352 + ntp * 32 + vlane);
                mma16(o[ntp * 2],     a, vb[0], vb[1]);
                mma16(o[ntp * 2 + 1], a, vb[2], vb[3]);
            }
        }
    }
#undef LOADK
#undef LOADV

    // normalize + write ctx (half, for the dense GEMM)
    const float inv0 = 1.f / lst0, inv1 = 1.f / lst1;
#pragma unroll
    for (int nt = 0; nt < 16; nt++) {
        const int ccol = h * HDIM + nt * 8 + 2 * c;
        size_t r0 = ((size_t)((qb * 128 + m0 + g) * 2 + b)) * H_DIM + ccol;
        size_t r1 = ((size_t)((qb * 128 + m0 + g + 8) * 2 + b)) * H_DIM + ccol;
        *(__half2*)&g_ctx[r0] = __floats2half2_rn(o[nt][0] * inv0, o[nt][1] * inv0);
        *(__half2*)&g_ctx[r1] = __floats2half2_rn(o[nt][2] * inv1, o[nt][3] * inv1);
    }
}

// ---------------------------------------------------------------------------
extern "C" void kernel_launch(void* const* d_in, const int* in_sizes, int n_in,
                              void* d_out, int out_size)
{
    const float* hidden = (const float*)d_in[0];
    const float* rope   = (const float*)d_in[2];
    const float* Wqkv   = (const float*)d_in[3];
    const float* bqkv   = (const float*)d_in[4];
    const float* Wd     = (const float*)d_in[5];
    float* out = (float*)d_out;

    __half *mixed, *ctx, *hid, *wq, *wd;
    cudaGetSymbolAddress((void**)&mixed, g_mixed);
    cudaGetSymbolAddress((void**)&ctx,   g_ctx);
    cudaGetSymbolAddress((void**)&hid,   g_hid);
    cudaGetSymbolAddress((void**)&wq,    g_wq);
    cudaGetSymbolAddress((void**)&wd,    g_wd);

    cudaFuncSetAttribute(gemm_mma_kernel,
                         cudaFuncAttributeMaxDynamicSharedMemorySize, GEMM_SMEM);
    cudaFuncSetAttribute(flash_mma_kernel,
                         cudaFuncAttributeMaxDynamicSharedMemorySize, FLASH_SMEM);

    // fused fp16 pre-rounding (RNE) of all GEMM inputs — one launch
    {
        const int n0 = M_ROWS * H_DIM / 4;
        const int n1 = O_QKV * H_DIM / 4;
        const int n2 = H_DIM * H_DIM / 4;
        const int tot = n0 + n1 + n2;
        round_all_kernel<<<(tot + 255) / 256, 256>>>(
            (const float4*)hidden, (__half2*)hid, n0,
            (const float4*)Wqkv,   (__half2*)wq,  n1,
            (const float4*)Wd,     (__half2*)wd,  n2);
    }

    // 1) QKV projection + bias + fused RoPE (half output)
    gemm_mma_kernel<<<dim3(O_QKV / 256, M_ROWS / 128), 512, GEMM_SMEM>>>(
        hid, wq, bqkv, mixed, rope, O_QKV, H_DIM, 1);

    // 2) flash attention (fp16, ldmatrix K+V, balanced launch order)
    flash_mma_kernel<<<dim3(S_LEN / 128, NHEADS, B_SZ), 256, FLASH_SMEM>>>();

    // 3) dense projection (fp32 output, no rope)
    gemm_mma_kernel<<<dim3(H_DIM / 256, M_ROWS / 128), 512, GEMM_SMEM>>>(
        ctx, wd, nullptr, out, nullptr, H_DIM, H_DIM, 0);
}